// round 14
// baseline (speedup 1.0000x reference)
#include <cuda_runtime.h>
#include <math.h>
#include <stdint.h>

#define B_  4
#define T_  2048
#define E_  1024
#define H_  16
#define DH_ 64
#define BT_ (B_*T_)
#define BTE_ (B_*T_*E_)

// -------- scratch (device globals; no allocation allowed) --------
__device__ float g_Wall[4*E_*E_];     // folded+rounded wq* | wk* | wv | hq*  (* = row-permuted)
__device__ float g_Wcat[2*E_*E_];     // packed+rounded [proj|hp], rows of 2048
__device__ float g_xr[BTE_];          // tf32-rounded x
__device__ float g_q[BTE_];           // d-permuted (pairs adjacent)
__device__ float g_k[BTE_];           // d-permuted
__device__ float g_v[BTE_];           // NOT permuted
__device__ float g_qh[BTE_];          // d-permuted
__device__ float g_cat[BT_*2*E_];     // [attn | gate*ctx], rows of 2048 (unpermuted cols)
__device__ float g_K1[B_*64*E_];
__device__ float g_V1[B_*64*E_];
__device__ float g_K2[B_*32*E_];
__device__ float g_V2[B_*32*E_];

// -------- helpers --------
__device__ __forceinline__ uint32_t tf32u(float x) {
    uint32_t u;
    asm("cvt.rna.tf32.f32 %0, %1;" : "=r"(u) : "f"(x));
    return u;
}
__device__ __forceinline__ float tf32f(float x) { return __uint_as_float(tf32u(x)); }

// pair-permutation within 8-groups: original j -> slot 2*(j&3) + (j>>2)
// => original (tg, tg+4) land at adjacent slots (2tg, 2tg+1)
__device__ __forceinline__ int cperm(int n) {
    return (n & ~7) | (((n & 3) << 1) | ((n >> 2) & 1));
}

__device__ __forceinline__ void mma_tf32(float* c,
                                         uint32_t a0, uint32_t a1, uint32_t a2, uint32_t a3,
                                         uint32_t b0, uint32_t b1) {
    asm volatile(
        "mma.sync.aligned.m16n8k8.row.col.f32.tf32.tf32.f32 "
        "{%0,%1,%2,%3},{%4,%5,%6,%7},{%8,%9},{%0,%1,%2,%3};"
        : "+f"(c[0]), "+f"(c[1]), "+f"(c[2]), "+f"(c[3])
        : "r"(a0), "r"(a1), "r"(a2), "r"(a3), "r"(b0), "r"(b1));
}

__device__ __forceinline__ void cp_async16(uint32_t smem_addr, const void* gptr) {
    asm volatile("cp.async.cg.shared.global [%0], [%1], 16;\n"
                 :: "r"(smem_addr), "l"(gptr));
}
__device__ __forceinline__ void cp_commit() {
    asm volatile("cp.async.commit_group;\n");
}
__device__ __forceinline__ void cp_wait1() {
    asm volatile("cp.async.wait_group 1;\n");
}

// -------- fold LoRA (tf32-rounded); optional row permutation --------
__global__ void fold_lora_kernel(const float* __restrict__ W,
                                 const float* __restrict__ A,
                                 const float* __restrict__ Bm,
                                 float* __restrict__ Weff, int permute) {
    int idx = blockIdx.x * blockDim.x + threadIdx.x;
    int n = idx >> 10;
    int k = idx & 1023;
    float acc = W[idx];
    #pragma unroll
    for (int r = 0; r < 8; ++r)
        acc += 2.0f * A[n * 8 + r] * Bm[r * E_ + k];
    int nd = permute ? cperm(n) : n;
    Weff[(size_t)nd * E_ + k] = tf32f(acc);
}

// -------- elementwise tf32 rounding (no perm) --------
__global__ void round_tf32_kernel(const float* __restrict__ src, float* __restrict__ dst) {
    int i = blockIdx.x * blockDim.x + threadIdx.x;
    float4 v = ((const float4*)src)[i];
    ((float4*)dst)[i] = make_float4(tf32f(v.x), tf32f(v.y), tf32f(v.z), tf32f(v.w));
}

// -------- round + row-permute (for hq); float4, coalesced --------
__global__ void round_permrow_kernel(const float* __restrict__ src, float* __restrict__ dst) {
    int i = blockIdx.x * blockDim.x + threadIdx.x;   // float4 over E*E/4
    int n = i >> 8;
    int kq = (i & 255) << 2;
    float4 v = *(const float4*)(src + (size_t)n * E_ + kq);
    *(float4*)(dst + (size_t)cperm(n) * E_ + kq) =
        make_float4(tf32f(v.x), tf32f(v.y), tf32f(v.z), tf32f(v.w));
}

// -------- pack epilogue weights: Wcat[n] = [rna(proj[n]) | rna(hp[n])] --------
__global__ void pack_weights_kernel(const float* __restrict__ proj,
                                    const float* __restrict__ hp,
                                    float* __restrict__ Wcat) {
    int i = blockIdx.x * blockDim.x + threadIdx.x;
    int n = i >> 8;
    int kq = (i & 255) << 2;
    float4 p = *(const float4*)(proj + (size_t)n * E_ + kq);
    float4 h = *(const float4*)(hp   + (size_t)n * E_ + kq);
    *(float4*)(Wcat + (size_t)n * 2 * E_ + kq) =
        make_float4(tf32f(p.x), tf32f(p.y), tf32f(p.z), tf32f(p.w));
    *(float4*)(Wcat + (size_t)n * 2 * E_ + E_ + kq) =
        make_float4(tf32f(h.x), tf32f(h.y), tf32f(h.z), tf32f(h.w));
}

// ====== tf32 GEMM: 3-stage cp.async pipeline (unchanged hot loop) ======
#define GBM 128
#define GBK 32
#define GST 36
#define GBUF_FLOATS (128*GST)
#define GBUF_BYTES  (GBUF_FLOATS*4)
#define GEMM_SMEM_BYTES (6*GBUF_BYTES)   // 110592

__global__ void __launch_bounds__(256, 2)
gemm_tf32_nt_kernel(const float* __restrict__ A, const float* __restrict__ Bmat,
                    float* __restrict__ C0, float* __restrict__ C1,
                    float* __restrict__ C2, float* __restrict__ C3,
                    int K, int round_out) {
    extern __shared__ float sm[];
    const uint32_t sbase = (uint32_t)__cvta_generic_to_shared(sm);
    const uint32_t bbase = sbase + 3u * GBUF_BYTES;

    const int tid  = threadIdx.x;
    const int warp = tid >> 5;
    const int lane = tid & 31;
    const int wm = warp >> 2;
    const int wn = warp & 3;
    const int g  = lane >> 2;
    const int tg = lane & 3;

    const int bm = blockIdx.y * GBM;
    const int cb = blockIdx.x;
    const int bnW = cb * 128;
    float* Cbuf = (cb < 8) ? C0 : (cb < 16) ? C1 : (cb < 24) ? C2 : C3;
    const int bnC = (cb & 7) * 128;

    float c[4][4][4];
    #pragma unroll
    for (int i = 0; i < 4; ++i)
        #pragma unroll
        for (int j = 0; j < 4; ++j)
            #pragma unroll
            for (int r = 0; r < 4; ++r) c[i][j][r] = 0.0f;

    int lm[4], lkq[4];
    #pragma unroll
    for (int u = 0; u < 4; ++u) {
        int lin = tid + u * 256;
        lm[u]  = lin >> 3;
        lkq[u] = (lin & 7) << 2;
    }

    const int NT = K / GBK;

    #pragma unroll 1
    for (int s = 0; s < 2; ++s) {
        const int kb = s * GBK;
        const uint32_t off = (uint32_t)(s * GBUF_BYTES);
        #pragma unroll
        for (int u = 0; u < 4; ++u) {
            uint32_t da = sbase + off + (uint32_t)(lm[u] * 144 + lkq[u] * 4);
            uint32_t db = bbase + off + (uint32_t)(lm[u] * 144 + lkq[u] * 4);
            cp_async16(da, A    + (size_t)(bm  + lm[u]) * K + kb + lkq[u]);
            cp_async16(db, Bmat + (size_t)(bnW + lm[u]) * K + kb + lkq[u]);
        }
        cp_commit();
    }

    int sc = 0, sw = 2;
    for (int kt = 0; kt < NT; ++kt) {
        cp_wait1();
        __syncthreads();

        if (kt + 2 < NT) {
            const int kb = (kt + 2) * GBK;
            const uint32_t off = (uint32_t)(sw * GBUF_BYTES);
            #pragma unroll
            for (int u = 0; u < 4; ++u) {
                uint32_t da = sbase + off + (uint32_t)(lm[u] * 144 + lkq[u] * 4);
                uint32_t db = bbase + off + (uint32_t)(lm[u] * 144 + lkq[u] * 4);
                cp_async16(da, A    + (size_t)(bm  + lm[u]) * K + kb + lkq[u]);
                cp_async16(db, Bmat + (size_t)(bnW + lm[u]) * K + kb + lkq[u]);
            }
            cp_commit();
            if (++sw == 3) sw = 0;
        }

        const float* Ab = sm + sc * GBUF_FLOATS;
        const float* Bb = sm + 3 * GBUF_FLOATS + sc * GBUF_FLOATS;
        #pragma unroll
        for (int ks = 0; ks < GBK; ks += 8) {
            uint32_t af[4][4], bf[4][2];
            #pragma unroll
            for (int mt = 0; mt < 4; ++mt) {
                int m = wm * 64 + mt * 16;
                af[mt][0] = __float_as_uint(Ab[(m + g    ) * GST + ks + tg    ]);
                af[mt][1] = __float_as_uint(Ab[(m + g + 8) * GST + ks + tg    ]);
                af[mt][2] = __float_as_uint(Ab[(m + g    ) * GST + ks + tg + 4]);
                af[mt][3] = __float_as_uint(Ab[(m + g + 8) * GST + ks + tg + 4]);
            }
            #pragma unroll
            for (int nt = 0; nt < 4; ++nt) {
                int n = wn * 32 + nt * 8;
                bf[nt][0] = __float_as_uint(Bb[(n + g) * GST + ks + tg    ]);
                bf[nt][1] = __float_as_uint(Bb[(n + g) * GST + ks + tg + 4]);
            }
            #pragma unroll
            for (int mt = 0; mt < 4; ++mt)
                #pragma unroll
                for (int nt = 0; nt < 4; ++nt)
                    mma_tf32(c[mt][nt], af[mt][0], af[mt][1], af[mt][2], af[mt][3],
                             bf[nt][0], bf[nt][1]);
        }
        if (++sc == 3) sc = 0;
    }

    #pragma unroll
    for (int mt = 0; mt < 4; ++mt) {
        #pragma unroll
        for (int nt = 0; nt < 4; ++nt) {
            int row0 = bm + wm * 64 + mt * 16 + g;
            int col  = bnC + wn * 32 + nt * 8 + tg * 2;
            float* p0 = Cbuf + (size_t)row0 * E_ + col;
            float* p1 = Cbuf + (size_t)(row0 + 8) * E_ + col;
            float v0 = c[mt][nt][0];
            float v1 = c[mt][nt][1];
            float v2 = c[mt][nt][2];
            float v3 = c[mt][nt][3];
            if (round_out) { v0 = tf32f(v0); v1 = tf32f(v1); v2 = tf32f(v2); v3 = tf32f(v3); }
            p0[0] = v0; p0[1] = v1; p1[0] = v2; p1[1] = v3;
        }
    }
}

// ====== flash attention: 3-stage cp.async; Q/K d-permuted -> LDS.64 frags ======
#define FKSTR 72
#define FVSTR 72
#define FKBUF (64*FKSTR)
#define FVBUF (64*FVSTR)
#define FLASH_SMEM_BYTES (3*(FKBUF+FVBUF)*4)   // 110592

__global__ void __launch_bounds__(256, 2)
flash_tf32_kernel(const float* __restrict__ Q, const float* __restrict__ K,
                  const float* __restrict__ V, const float* __restrict__ slopes,
                  float* __restrict__ O) {
    extern __shared__ float fsm[];
    const uint32_t sbase = (uint32_t)__cvta_generic_to_shared(fsm);
    const uint32_t vbase = sbase + 3u * FKBUF * 4u;
    float* Vsm = fsm + 3 * FKBUF;

    const int bh = blockIdx.y;
    const int b = bh >> 4;
    const int h = bh & 15;
    const int bx = (int)gridDim.x - 1 - (int)blockIdx.x;   // heavy blocks first
    const int q0 = bx * 128;
    const int tid = threadIdx.x;
    const int warp = tid >> 5;
    const int lane = tid & 31;
    const int g = lane >> 2;
    const int tg = lane & 3;
    const float slope = slopes[h];

    const int srow = tid >> 2;
    const int scol = (tid & 3) * 16;

    // ---- stage Q halves (d-permuted), pick fragments as LDS.64 pairs ----
    uint32_t qf[8][4];
    #pragma unroll 1
    for (int half = 0; half < 2; ++half) {
        const float* src = Q + ((size_t)(b * T_ + q0 + half * 64 + srow)) * E_ + h * 64 + scol;
        #pragma unroll
        for (int u = 0; u < 4; ++u)
            *(float4*)&fsm[srow * FKSTR + scol + u * 4] = *(const float4*)(src + u * 4);
        __syncthreads();
        if ((warp >> 2) == half) {
            int lr = (warp & 3) * 16;
            #pragma unroll
            for (int cc = 0; cc < 8; ++cc) {
                float2 x = *(const float2*)&fsm[(lr + g    ) * FKSTR + cc * 8 + tg * 2];
                float2 y = *(const float2*)&fsm[(lr + g + 8) * FKSTR + cc * 8 + tg * 2];
                qf[cc][0] = __float_as_uint(x.x);   // k = tg
                qf[cc][2] = __float_as_uint(x.y);   // k = tg+4
                qf[cc][1] = __float_as_uint(y.x);
                qf[cc][3] = __float_as_uint(y.y);
            }
        }
        __syncthreads();
    }

    float o[8][4];
    #pragma unroll
    for (int dt = 0; dt < 8; ++dt)
        #pragma unroll
        for (int r = 0; r < 4; ++r) o[dt][r] = 0.0f;

    float m0 = -1e30f, m1 = -1e30f, l0 = 0.0f, l1 = 0.0f;
    const int r0 = q0 + warp * 16 + g;
    const int r1 = r0 + 8;
    const int lastjt_w = 2 * bx + (warp >= 4 ? 1 : 0);
    const int lastjt = 2 * bx + 1;

    #pragma unroll 1
    for (int s = 0; s < 2; ++s) {
        const int nb = s * 64;
        const float* ksrc = K + ((size_t)(b * T_ + nb + srow)) * E_ + h * 64 + scol;
        const float* vsrc = V + ((size_t)(b * T_ + nb + srow)) * E_ + h * 64 + scol;
        uint32_t kd = sbase + (uint32_t)((s * FKBUF + srow * FKSTR + scol) * 4);
        uint32_t vd = vbase + (uint32_t)((s * FVBUF + srow * FVSTR + scol) * 4);
        #pragma unroll
        for (int u = 0; u < 4; ++u) {
            cp_async16(kd + u * 16, ksrc + u * 4);
            cp_async16(vd + u * 16, vsrc + u * 4);
        }
        cp_commit();
    }

    int sc = 0, sw = 2;
    for (int jt = 0; jt <= lastjt; ++jt) {
        cp_wait1();
        __syncthreads();

        if (jt + 2 <= lastjt) {
            const int n1 = (jt + 2) * 64;
            const float* ksrc = K + ((size_t)(b * T_ + n1 + srow)) * E_ + h * 64 + scol;
            const float* vsrc = V + ((size_t)(b * T_ + n1 + srow)) * E_ + h * 64 + scol;
            uint32_t kd = sbase + (uint32_t)((sw * FKBUF + srow * FKSTR + scol) * 4);
            uint32_t vd = vbase + (uint32_t)((sw * FVBUF + srow * FVSTR + scol) * 4);
            #pragma unroll
            for (int u = 0; u < 4; ++u) {
                cp_async16(kd + u * 16, ksrc + u * 4);
                cp_async16(vd + u * 16, vsrc + u * 4);
            }
            cp_commit();
            if (++sw == 3) sw = 0;
        }

        if (jt <= lastjt_w) {
            const int n0 = jt * 64;
            const float* Kb = fsm + sc * FKBUF;
            const float* Vb = Vsm + sc * FVBUF;

            float sa[8][4];
            #pragma unroll
            for (int nt = 0; nt < 8; ++nt)
                #pragma unroll
                for (int r = 0; r < 4; ++r) sa[nt][r] = 0.0f;
            #pragma unroll
            for (int cc = 0; cc < 8; ++cc) {
                #pragma unroll
                for (int nt = 0; nt < 8; ++nt) {
                    float2 z = *(const float2*)(Kb + (nt * 8 + g) * FKSTR + cc * 8 + tg * 2);
                    mma_tf32(sa[nt], qf[cc][0], qf[cc][1], qf[cc][2], qf[cc][3],
                             __float_as_uint(z.x), __float_as_uint(z.y));
                }
            }

            float mx0 = -1e30f, mx1 = -1e30f;
            const bool diag = (jt == lastjt_w);
            #pragma unroll
            for (int nt = 0; nt < 8; ++nt) {
                int kc0 = n0 + nt * 8 + tg * 2;
                float a00 = slope * (float)(r0 - kc0);
                float a01 = a00 - slope;
                float a10 = slope * (float)(r1 - kc0);
                float a11 = a10 - slope;
                float v00 = fmaf(sa[nt][0], 0.125f, a00);
                float v01 = fmaf(sa[nt][1], 0.125f, a01);
                float v10 = fmaf(sa[nt][2], 0.125f, a10);
                float v11 = fmaf(sa[nt][3], 0.125f, a11);
                if (diag) {
                    if (kc0     > r0) v00 = -1e30f;
                    if (kc0 + 1 > r0) v01 = -1e30f;
                    if (kc0     > r1) v10 = -1e30f;
                    if (kc0 + 1 > r1) v11 = -1e30f;
                }
                sa[nt][0] = v00; sa[nt][1] = v01; sa[nt][2] = v10; sa[nt][3] = v11;
                mx0 = fmaxf(mx0, fmaxf(v00, v01));
                mx1 = fmaxf(mx1, fmaxf(v10, v11));
            }
            mx0 = fmaxf(mx0, __shfl_xor_sync(0xffffffffu, mx0, 1));
            mx0 = fmaxf(mx0, __shfl_xor_sync(0xffffffffu, mx0, 2));
            mx1 = fmaxf(mx1, __shfl_xor_sync(0xffffffffu, mx1, 1));
            mx1 = fmaxf(mx1, __shfl_xor_sync(0xffffffffu, mx1, 2));

            float mn0 = fmaxf(m0, mx0);
            float mn1 = fmaxf(m1, mx1);
            float sc0 = __expf(m0 - mn0);
            float sc1 = __expf(m1 - mn1);
            float rs0 = 0.0f, rs1 = 0.0f;
            #pragma unroll
            for (int nt = 0; nt < 8; ++nt) {
                float p00 = tf32f(__expf(sa[nt][0] - mn0));
                float p01 = tf32f(__expf(sa[nt][1] - mn0));
                float p10 = tf32f(__expf(sa[nt][2] - mn1));
                float p11 = tf32f(__expf(sa[nt][3] - mn1));
                rs0 += p00 + p01;
                rs1 += p10 + p11;
                sa[nt][0] = p00; sa[nt][1] = p01; sa[nt][2] = p10; sa[nt][3] = p11;
            }
            rs0 += __shfl_xor_sync(0xffffffffu, rs0, 1);
            rs0 += __shfl_xor_sync(0xffffffffu, rs0, 2);
            rs1 += __shfl_xor_sync(0xffffffffu, rs1, 1);
            rs1 += __shfl_xor_sync(0xffffffffu, rs1, 2);

            l0 = l0 * sc0 + rs0;
            l1 = l1 * sc1 + rs1;
            m0 = mn0; m1 = mn1;
            #pragma unroll
            for (int dt = 0; dt < 8; ++dt) {
                o[dt][0] *= sc0; o[dt][1] *= sc0;
                o[dt][2] *= sc1; o[dt][3] *= sc1;
            }

            #pragma unroll
            for (int kc = 0; kc < 8; ++kc) {
                int srcA = (lane & 28) + (tg >> 1);
                int srcB = srcA + 2;
                float s00 = __shfl_sync(0xffffffffu, sa[kc][0], srcA);
                float s01 = __shfl_sync(0xffffffffu, sa[kc][1], srcA);
                float s02 = __shfl_sync(0xffffffffu, sa[kc][2], srcA);
                float s03 = __shfl_sync(0xffffffffu, sa[kc][3], srcA);
                float s10 = __shfl_sync(0xffffffffu, sa[kc][0], srcB);
                float s11 = __shfl_sync(0xffffffffu, sa[kc][1], srcB);
                float s12 = __shfl_sync(0xffffffffu, sa[kc][2], srcB);
                float s13 = __shfl_sync(0xffffffffu, sa[kc][3], srcB);
                const bool odd = (tg & 1);
                uint32_t a0 = __float_as_uint(odd ? s01 : s00);
                uint32_t a1 = __float_as_uint(odd ? s03 : s02);
                uint32_t a2 = __float_as_uint(odd ? s11 : s10);
                uint32_t a3 = __float_as_uint(odd ? s13 : s12);
                #pragma unroll
                for (int dt = 0; dt < 8; ++dt) {
                    uint32_t b0 = __float_as_uint(Vb[(kc * 8 + tg    ) * FVSTR + dt * 8 + g]);
                    uint32_t b1 = __float_as_uint(Vb[(kc * 8 + tg + 4) * FVSTR + dt * 8 + g]);
                    mma_tf32(o[dt], a0, a1, a2, a3, b0, b1);
                }
            }
        }
        if (++sc == 3) sc = 0;
    }

    // write attn into cat[:, 0:1024], tf32-rounded (row stride 2048, cols unpermuted)
    float il0 = 1.0f / l0, il1 = 1.0f / l1;
    #pragma unroll
    for (int dt = 0; dt < 8; ++dt) {
        float* d0 = O + ((size_t)(b * T_ + r0)) * (2 * E_) + h * 64 + dt * 8 + tg * 2;
        float* d1 = O + ((size_t)(b * T_ + r1)) * (2 * E_) + h * 64 + dt * 8 + tg * 2;
        *(float2*)d0 = make_float2(tf32f(o[dt][0] * il0), tf32f(o[dt][1] * il0));
        *(float2*)d1 = make_float2(tf32f(o[dt][2] * il1), tf32f(o[dt][3] * il1));
    }
}

// -------- merged hierarchy pooling (elementwise; perm-transparent) --------
__global__ void pool_kernel(const float* __restrict__ Kf, const float* __restrict__ Vf,
                            float* __restrict__ K1, float* __restrict__ V1,
                            float* __restrict__ K2, float* __restrict__ V2) {
    int idx = blockIdx.x * blockDim.x + threadIdx.x;
    if (idx >= B_ * 32 * E_) return;
    int e = idx & (E_ - 1);
    int p = (idx >> 10) & 31;
    int b = idx >> 15;

    float k1a = 0.0f, v1a = 0.0f, k1b = 0.0f, v1b = 0.0f;
    {
        int t0 = (32 + 2 * p) * 16;
        #pragma unroll
        for (int u = 0; u < 16; ++u) {
            size_t off = ((size_t)(b * T_ + t0 + u) * E_) + e;
            k1a += Kf[off]; v1a += Vf[off];
        }
        t0 += 16;
        #pragma unroll
        for (int u = 0; u < 16; ++u) {
            size_t off = ((size_t)(b * T_ + t0 + u) * E_) + e;
            k1b += Kf[off]; v1b += Vf[off];
        }
    }
    k1a *= (1.0f / 16.0f); v1a *= (1.0f / 16.0f);
    k1b *= (1.0f / 16.0f); v1b *= (1.0f / 16.0f);

    size_t o1 = ((size_t)(b * 64 + 2 * p)) * E_ + e;
    K1[o1] = k1a;        V1[o1] = v1a;
    K1[o1 + E_] = k1b;   V1[o1 + E_] = v1b;

    K2[idx] = 0.5f * (k1a + k1b);
    V2[idx] = 0.5f * (v1a + v1b);
}

// ============ hierarchical attention (dots invariant: qh & K1 both permuted) ============
__global__ void __launch_bounds__(128)
hier_attn_kernel(const float* __restrict__ Qh,
                 const float* __restrict__ K1, const float* __restrict__ V1,
                 const float* __restrict__ K2, const float* __restrict__ V2,
                 const float* __restrict__ gate,
                 float* __restrict__ cat) {
    __shared__ float Qs[32][65];
    __shared__ float KV[96][68];
    __shared__ float Ss[32][97];

    const int bh = blockIdx.y;
    const int b = bh >> 4;
    const int h = bh & 15;
    const int t0 = blockIdx.x * 32;
    const int tid = threadIdx.x;
    const int q = tid >> 2;
    const int qt = tid & 3;
    const int qc = qt * 16;

    const float gsig = 1.0f / (1.0f + __expf(-__ldg(gate)));

    for (int i = tid; i < 32 * 16; i += 128) {
        int r = i >> 4, c4 = (i & 15) << 2;
        float4 v = *(const float4*)(Qh + ((size_t)(b * T_ + t0 + r)) * E_ + h * 64 + c4);
        Qs[r][c4] = v.x; Qs[r][c4 + 1] = v.y; Qs[r][c4 + 2] = v.z; Qs[r][c4 + 3] = v.w;
    }
    for (int i = tid; i < 96 * 16; i += 128) {
        int r = i >> 4, c4 = (i & 15) << 2;
        const float* src = (r < 64)
            ? (K1 + ((size_t)(b * 64 + r)) * E_ + h * 64 + c4)
            : (K2 + ((size_t)(b * 32 + r - 64)) * E_ + h * 64 + c4);
        *(float4*)&KV[r][c4] = *(const float4*)src;
    }
    __syncthreads();

    for (int m = 0; m < 96; ++m) {
        float s = 0.0f;
        #pragma unroll
        for (int d = 0; d < 16; ++d)
            s = fmaf(Qs[q][qc + d], KV[m][qc + d], s);
        s += __shfl_xor_sync(0xffffffffu, s, 1);
        s += __shfl_xor_sync(0xffffffffu, s, 2);
        if (qt == 0) Ss[q][m] = s * 0.125f;
    }
    __syncthreads();

    for (int i = tid; i < 96 * 16; i += 128) {
        int r = i >> 4, c4 = (i & 15) << 2;
        const float* src = (r < 64)
            ? (V1 + ((size_t)(b * 64 + r)) * E_ + h * 64 + c4)
            : (V2 + ((size_t)(b * 32 + r - 64)) * E_ + h * 64 + c4);
        *(float4*)&KV[r][c4] = *(const float4*)src;
    }
    __syncthreads();

    float mx1 = -1e30f;
    for (int m = 0; m < 64; ++m) mx1 = fmaxf(mx1, Ss[q][m]);
    float o1[16];
    #pragma unroll
    for (int d = 0; d < 16; ++d) o1[d] = 0.0f;
    float sum1 = 0.0f;
    for (int m = 0; m < 64; ++m) {
        float p = __expf(Ss[q][m] - mx1);
        sum1 += p;
        #pragma unroll
        for (int d = 0; d < 16; ++d) o1[d] = fmaf(p, KV[m][qc + d], o1[d]);
    }
    float mx2 = -1e30f;
    for (int m = 64; m < 96; ++m) mx2 = fmaxf(mx2, Ss[q][m]);
    float o2[16];
    #pragma unroll
    for (int d = 0; d < 16; ++d) o2[d] = 0.0f;
    float sum2 = 0.0f;
    for (int m = 64; m < 96; ++m) {
        float p = __expf(Ss[q][m] - mx2);
        sum2 += p;
        #pragma unroll
        for (int d = 0; d < 16; ++d) o2[d] = fmaf(p, KV[m][qc + d], o2[d]);
    }
    float inv1 = gsig / sum1, inv2 = gsig / sum2;

    float* dst = cat + ((size_t)(b * T_ + t0 + q)) * (2 * E_) + E_ + h * 64 + qc;
    #pragma unroll
    for (int d4 = 0; d4 < 16; d4 += 4) {
        *(float4*)(dst + d4) = make_float4(
            tf32f(o1[d4 + 0] * inv1 + o2[d4 + 0] * inv2),
            tf32f(o1[d4 + 1] * inv1 + o2[d4 + 1] * inv2),
            tf32f(o1[d4 + 2] * inv1 + o2[d4 + 2] * inv2),
            tf32f(o1[d4 + 3] * inv1 + o2[d4 + 3] * inv2));
    }
}

__global__ void zero_tail_kernel(float* p, int n) {
    int i = blockIdx.x * blockDim.x + threadIdx.x;
    if (i < n) p[i] = 0.0f;
}

// -------- launch --------
extern "C" void kernel_launch(void* const* d_in, const int* in_sizes, int n_in,
                              void* d_out, int out_size) {
    const float* x      = (const float*)d_in[0];
    const float* Wq_w   = (const float*)d_in[1];
    const float* Wq_A   = (const float*)d_in[2];
    const float* Wq_B   = (const float*)d_in[3];
    const float* Wk_w   = (const float*)d_in[4];
    const float* Wk_A   = (const float*)d_in[5];
    const float* Wk_B   = (const float*)d_in[6];
    const float* Wv_w   = (const float*)d_in[7];
    const float* Wv_A   = (const float*)d_in[8];
    const float* Wv_B   = (const float*)d_in[9];
    const float* proj_w = (const float*)d_in[10];
    const float* hq_w   = (const float*)d_in[11];
    const float* hp_w   = (const float*)d_in[12];
    const float* gate   = (const float*)d_in[13];
    const float* slopes = (const float*)d_in[14];
    float* out = (float*)d_out;

    float *wall, *wcat, *xr, *q, *k, *v, *qh, *cat, *K1, *V1, *K2, *V2;
    cudaGetSymbolAddress((void**)&wall, g_Wall);
    cudaGetSymbolAddress((void**)&wcat, g_Wcat);
    cudaGetSymbolAddress((void**)&xr, g_xr);
    cudaGetSymbolAddress((void**)&q, g_q);
    cudaGetSymbolAddress((void**)&k, g_k);
    cudaGetSymbolAddress((void**)&v, g_v);
    cudaGetSymbolAddress((void**)&qh, g_qh);
    cudaGetSymbolAddress((void**)&cat, g_cat);
    cudaGetSymbolAddress((void**)&K1, g_K1);
    cudaGetSymbolAddress((void**)&V1, g_V1);
    cudaGetSymbolAddress((void**)&K2, g_K2);
    cudaGetSymbolAddress((void**)&V2, g_V2);

    cudaFuncSetAttribute(gemm_tf32_nt_kernel,
                         cudaFuncAttributeMaxDynamicSharedMemorySize, GEMM_SMEM_BYTES);
    cudaFuncSetAttribute(flash_tf32_kernel,
                         cudaFuncAttributeMaxDynamicSharedMemorySize, FLASH_SMEM_BYTES);

    // 1. pre-round inputs; wq/wk/hq rows permuted (pairs-adjacent d for flash/hier)
    fold_lora_kernel<<<(E_ * E_) / 256, 256>>>(Wq_w, Wq_A, Wq_B, wall, 1);
    fold_lora_kernel<<<(E_ * E_) / 256, 256>>>(Wk_w, Wk_A, Wk_B, wall + E_ * E_, 1);
    fold_lora_kernel<<<(E_ * E_) / 256, 256>>>(Wv_w, Wv_A, Wv_B, wall + 2 * E_ * E_, 0);
    round_permrow_kernel<<<(E_ * E_ / 4) / 256, 256>>>(hq_w, wall + 3 * E_ * E_);
    round_tf32_kernel<<<(BTE_ / 4) / 256, 256>>>(x, xr);

    // 2. merged projection GEMM (outputs tf32-rounded; q/k/qh d-permuted via rows)
    gemm_tf32_nt_kernel<<<dim3(32, BT_ / GBM), 256, GEMM_SMEM_BYTES>>>(
        xr, wall, q, k, v, qh, E_, 1);

    // 3. causal attention with alibi -> cat[:, 0:1024]
    flash_tf32_kernel<<<dim3(T_ / 128, B_ * H_), 256, FLASH_SMEM_BYTES>>>(
        q, k, v, slopes, cat);

    // 4. merged hierarchy pooling + small attention -> cat[:, 1024:2048] (gated)
    pool_kernel<<<(B_ * 32 * E_ + 255) / 256, 256>>>(k, v, K1, V1, K2, V2);
    hier_attn_kernel<<<dim3(T_ / 32, B_ * H_), 128>>>(qh, K1, V1, K2, V2, gate, cat);

    // 5. pack epilogue weights and ONE merged epilogue GEMM (K = 2048)
    pack_weights_kernel<<<(E_ * E_ / 4) / 256, 256>>>(proj_w, hp_w, wcat);
    gemm_tf32_nt_kernel<<<dim3(8, BT_ / GBM), 256, GEMM_SMEM_BYTES>>>(
        cat, wcat, out, out, out, out, 2 * E_, 0);

    // 6. recon output is exactly zero
    if (out_size > BTE_) {
        int tail = out_size - BTE_;
        zero_tail_kernel<<<(tail + 255) / 256, 256>>>(out + BTE_, tail);
    }
}

// round 15
// speedup vs baseline: 1.0209x; 1.0209x over previous
#include <cuda_runtime.h>
#include <math.h>
#include <stdint.h>

#define B_  4
#define T_  2048
#define E_  1024
#define H_  16
#define DH_ 64
#define BT_ (B_*T_)
#define BTE_ (B_*T_*E_)

// -------- scratch (device globals; no allocation allowed) --------
__device__ float g_Wall[4*E_*E_];     // folded+rounded wq* | wk* | wv | hq*  (* = row-permuted)
__device__ float g_Wcat[2*E_*E_];     // packed+rounded [proj|hp], rows of 2048
__device__ float g_xr[BTE_];          // tf32-rounded x
__device__ float g_q[BTE_];           // d-permuted (pairs adjacent)
__device__ float g_k[BTE_];           // d-permuted
__device__ float g_v[BTE_];           // NOT permuted
__device__ float g_qh[BTE_];          // d-permuted
__device__ float g_cat[BT_*2*E_];     // [attn | gate*ctx], rows of 2048
__device__ float g_K1[B_*64*E_];
__device__ float g_V1[B_*64*E_];
__device__ float g_K2[B_*32*E_];
__device__ float g_V2[B_*32*E_];

// -------- helpers --------
__device__ __forceinline__ uint32_t tf32u(float x) {
    uint32_t u;
    asm("cvt.rna.tf32.f32 %0, %1;" : "=r"(u) : "f"(x));
    return u;
}
__device__ __forceinline__ float tf32f(float x) { return __uint_as_float(tf32u(x)); }

// pair-permutation within 8-groups: j -> 2*(j&3) + (j>>2)
__device__ __forceinline__ int cperm(int n) {
    return (n & ~7) | (((n & 3) << 1) | ((n >> 2) & 1));
}

__device__ __forceinline__ void mma_tf32(float* c,
                                         uint32_t a0, uint32_t a1, uint32_t a2, uint32_t a3,
                                         uint32_t b0, uint32_t b1) {
    asm volatile(
        "mma.sync.aligned.m16n8k8.row.col.f32.tf32.tf32.f32 "
        "{%0,%1,%2,%3},{%4,%5,%6,%7},{%8,%9},{%0,%1,%2,%3};"
        : "+f"(c[0]), "+f"(c[1]), "+f"(c[2]), "+f"(c[3])
        : "r"(a0), "r"(a1), "r"(a2), "r"(a3), "r"(b0), "r"(b1));
}

__device__ __forceinline__ void cp_async16(uint32_t smem_addr, const void* gptr) {
    asm volatile("cp.async.cg.shared.global [%0], [%1], 16;\n"
                 :: "r"(smem_addr), "l"(gptr));
}
__device__ __forceinline__ void cp_commit() {
    asm volatile("cp.async.commit_group;\n");
}
__device__ __forceinline__ void cp_wait1() {
    asm volatile("cp.async.wait_group 1;\n");
}

// -------- fold LoRA (tf32-rounded); optional row permutation --------
__global__ void fold_lora_kernel(const float* __restrict__ W,
                                 const float* __restrict__ A,
                                 const float* __restrict__ Bm,
                                 float* __restrict__ Weff, int permute) {
    int idx = blockIdx.x * blockDim.x + threadIdx.x;
    int n = idx >> 10;
    int k = idx & 1023;
    float acc = W[idx];
    #pragma unroll
    for (int r = 0; r < 8; ++r)
        acc += 2.0f * A[n * 8 + r] * Bm[r * E_ + k];
    int nd = permute ? cperm(n) : n;
    Weff[(size_t)nd * E_ + k] = tf32f(acc);
}

// -------- elementwise tf32 rounding --------
__global__ void round_tf32_kernel(const float* __restrict__ src, float* __restrict__ dst) {
    int i = blockIdx.x * blockDim.x + threadIdx.x;
    float4 v = ((const float4*)src)[i];
    ((float4*)dst)[i] = make_float4(tf32f(v.x), tf32f(v.y), tf32f(v.z), tf32f(v.w));
}

// -------- round + row-permute (for hq) --------
__global__ void round_permrow_kernel(const float* __restrict__ src, float* __restrict__ dst) {
    int i = blockIdx.x * blockDim.x + threadIdx.x;
    int n = i >> 8;
    int kq = (i & 255) << 2;
    float4 v = *(const float4*)(src + (size_t)n * E_ + kq);
    *(float4*)(dst + (size_t)cperm(n) * E_ + kq) =
        make_float4(tf32f(v.x), tf32f(v.y), tf32f(v.z), tf32f(v.w));
}

// -------- pack epilogue weights --------
__global__ void pack_weights_kernel(const float* __restrict__ proj,
                                    const float* __restrict__ hp,
                                    float* __restrict__ Wcat) {
    int i = blockIdx.x * blockDim.x + threadIdx.x;
    int n = i >> 8;
    int kq = (i & 255) << 2;
    float4 p = *(const float4*)(proj + (size_t)n * E_ + kq);
    float4 h = *(const float4*)(hp   + (size_t)n * E_ + kq);
    *(float4*)(Wcat + (size_t)n * 2 * E_ + kq) =
        make_float4(tf32f(p.x), tf32f(p.y), tf32f(p.z), tf32f(p.w));
    *(float4*)(Wcat + (size_t)n * 2 * E_ + E_ + kq) =
        make_float4(tf32f(h.x), tf32f(h.y), tf32f(h.z), tf32f(h.w));
}

// ====== tf32 GEMM: 3-stage cp.async pipeline (unchanged hot loop) ======
#define GBM 128
#define GBK 32
#define GST 36
#define GBUF_FLOATS (128*GST)
#define GBUF_BYTES  (GBUF_FLOATS*4)
#define GEMM_SMEM_BYTES (6*GBUF_BYTES)   // 110592

__global__ void __launch_bounds__(256, 2)
gemm_tf32_nt_kernel(const float* __restrict__ A, const float* __restrict__ Bmat,
                    float* __restrict__ C0, float* __restrict__ C1,
                    float* __restrict__ C2, float* __restrict__ C3,
                    int K, int round_out) {
    extern __shared__ float sm[];
    const uint32_t sbase = (uint32_t)__cvta_generic_to_shared(sm);
    const uint32_t bbase = sbase + 3u * GBUF_BYTES;

    const int tid  = threadIdx.x;
    const int warp = tid >> 5;
    const int lane = tid & 31;
    const int wm = warp >> 2;
    const int wn = warp & 3;
    const int g  = lane >> 2;
    const int tg = lane & 3;

    const int bm = blockIdx.y * GBM;
    const int cb = blockIdx.x;
    const int bnW = cb * 128;
    float* Cbuf = (cb < 8) ? C0 : (cb < 16) ? C1 : (cb < 24) ? C2 : C3;
    const int bnC = (cb & 7) * 128;

    float c[4][4][4];
    #pragma unroll
    for (int i = 0; i < 4; ++i)
        #pragma unroll
        for (int j = 0; j < 4; ++j)
            #pragma unroll
            for (int r = 0; r < 4; ++r) c[i][j][r] = 0.0f;

    int lm[4], lkq[4];
    #pragma unroll
    for (int u = 0; u < 4; ++u) {
        int lin = tid + u * 256;
        lm[u]  = lin >> 3;
        lkq[u] = (lin & 7) << 2;
    }

    const int NT = K / GBK;

    #pragma unroll 1
    for (int s = 0; s < 2; ++s) {
        const int kb = s * GBK;
        const uint32_t off = (uint32_t)(s * GBUF_BYTES);
        #pragma unroll
        for (int u = 0; u < 4; ++u) {
            uint32_t da = sbase + off + (uint32_t)(lm[u] * 144 + lkq[u] * 4);
            uint32_t db = bbase + off + (uint32_t)(lm[u] * 144 + lkq[u] * 4);
            cp_async16(da, A    + (size_t)(bm  + lm[u]) * K + kb + lkq[u]);
            cp_async16(db, Bmat + (size_t)(bnW + lm[u]) * K + kb + lkq[u]);
        }
        cp_commit();
    }

    int sc = 0, sw = 2;
    for (int kt = 0; kt < NT; ++kt) {
        cp_wait1();
        __syncthreads();

        if (kt + 2 < NT) {
            const int kb = (kt + 2) * GBK;
            const uint32_t off = (uint32_t)(sw * GBUF_BYTES);
            #pragma unroll
            for (int u = 0; u < 4; ++u) {
                uint32_t da = sbase + off + (uint32_t)(lm[u] * 144 + lkq[u] * 4);
                uint32_t db = bbase + off + (uint32_t)(lm[u] * 144 + lkq[u] * 4);
                cp_async16(da, A    + (size_t)(bm  + lm[u]) * K + kb + lkq[u]);
                cp_async16(db, Bmat + (size_t)(bnW + lm[u]) * K + kb + lkq[u]);
            }
            cp_commit();
            if (++sw == 3) sw = 0;
        }

        const float* Ab = sm + sc * GBUF_FLOATS;
        const float* Bb = sm + 3 * GBUF_FLOATS + sc * GBUF_FLOATS;
        #pragma unroll
        for (int ks = 0; ks < GBK; ks += 8) {
            uint32_t af[4][4], bf[4][2];
            #pragma unroll
            for (int mt = 0; mt < 4; ++mt) {
                int m = wm * 64 + mt * 16;
                af[mt][0] = __float_as_uint(Ab[(m + g    ) * GST + ks + tg    ]);
                af[mt][1] = __float_as_uint(Ab[(m + g + 8) * GST + ks + tg    ]);
                af[mt][2] = __float_as_uint(Ab[(m + g    ) * GST + ks + tg + 4]);
                af[mt][3] = __float_as_uint(Ab[(m + g + 8) * GST + ks + tg + 4]);
            }
            #pragma unroll
            for (int nt = 0; nt < 4; ++nt) {
                int n = wn * 32 + nt * 8;
                bf[nt][0] = __float_as_uint(Bb[(n + g) * GST + ks + tg    ]);
                bf[nt][1] = __float_as_uint(Bb[(n + g) * GST + ks + tg + 4]);
            }
            #pragma unroll
            for (int mt = 0; mt < 4; ++mt)
                #pragma unroll
                for (int nt = 0; nt < 4; ++nt)
                    mma_tf32(c[mt][nt], af[mt][0], af[mt][1], af[mt][2], af[mt][3],
                             bf[nt][0], bf[nt][1]);
        }
        if (++sc == 3) sc = 0;
    }

    #pragma unroll
    for (int mt = 0; mt < 4; ++mt) {
        #pragma unroll
        for (int nt = 0; nt < 4; ++nt) {
            int row0 = bm + wm * 64 + mt * 16 + g;
            int col  = bnC + wn * 32 + nt * 8 + tg * 2;
            float* p0 = Cbuf + (size_t)row0 * E_ + col;
            float* p1 = Cbuf + (size_t)(row0 + 8) * E_ + col;
            float v0 = c[mt][nt][0];
            float v1 = c[mt][nt][1];
            float v2 = c[mt][nt][2];
            float v3 = c[mt][nt][3];
            if (round_out) { v0 = tf32f(v0); v1 = tf32f(v1); v2 = tf32f(v2); v3 = tf32f(v3); }
            p0[0] = v0; p0[1] = v1; p1[0] = v2; p1[1] = v3;
        }
    }
}

// ====== flash attention: key-relabeled V -> P transpose is FREE ======
// V tile rows are loaded permuted: SMEM row slot r holds actual key κ(r)=cperm(r).
// The S/P C-fragment registers then ARE the PV A-fragment (a0=sa0,a1=sa2,a2=sa1,a3=sa3).
#define FKSTR 72
#define FVSTR 72
#define FKBUF (64*FKSTR)
#define FVBUF (64*FVSTR)
#define FLASH_SMEM_BYTES (3*(FKBUF+FVBUF)*4)   // 110592

__global__ void __launch_bounds__(256, 2)
flash_tf32_kernel(const float* __restrict__ Q, const float* __restrict__ K,
                  const float* __restrict__ V, const float* __restrict__ slopes,
                  float* __restrict__ O) {
    extern __shared__ float fsm[];
    const uint32_t sbase = (uint32_t)__cvta_generic_to_shared(fsm);
    const uint32_t vbase = sbase + 3u * FKBUF * 4u;
    float* Vsm = fsm + 3 * FKBUF;

    const int bh = blockIdx.y;
    const int b = bh >> 4;
    const int h = bh & 15;
    const int bx = (int)gridDim.x - 1 - (int)blockIdx.x;   // heavy blocks first
    const int q0 = bx * 128;
    const int tid = threadIdx.x;
    const int warp = tid >> 5;
    const int lane = tid & 31;
    const int g = lane >> 2;
    const int tg = lane & 3;
    const float slope = slopes[h];

    const int srow = tid >> 2;
    const int scol = (tid & 3) * 16;
    // V source row: slot srow holds actual key cperm-of-low-3-bits
    const int vrow = (srow & ~7) | (((srow & 3) << 1) | ((srow >> 2) & 1));

    // ---- stage Q halves (d-permuted), pick fragments as LDS.64 pairs ----
    uint32_t qf[8][4];
    #pragma unroll 1
    for (int half = 0; half < 2; ++half) {
        const float* src = Q + ((size_t)(b * T_ + q0 + half * 64 + srow)) * E_ + h * 64 + scol;
        #pragma unroll
        for (int u = 0; u < 4; ++u)
            *(float4*)&fsm[srow * FKSTR + scol + u * 4] = *(const float4*)(src + u * 4);
        __syncthreads();
        if ((warp >> 2) == half) {
            int lr = (warp & 3) * 16;
            #pragma unroll
            for (int cc = 0; cc < 8; ++cc) {
                float2 x = *(const float2*)&fsm[(lr + g    ) * FKSTR + cc * 8 + tg * 2];
                float2 y = *(const float2*)&fsm[(lr + g + 8) * FKSTR + cc * 8 + tg * 2];
                qf[cc][0] = __float_as_uint(x.x);
                qf[cc][2] = __float_as_uint(x.y);
                qf[cc][1] = __float_as_uint(y.x);
                qf[cc][3] = __float_as_uint(y.y);
            }
        }
        __syncthreads();
    }

    float o[8][4];
    #pragma unroll
    for (int dt = 0; dt < 8; ++dt)
        #pragma unroll
        for (int r = 0; r < 4; ++r) o[dt][r] = 0.0f;

    float m0 = -1e30f, m1 = -1e30f, l0 = 0.0f, l1 = 0.0f;
    const int r0 = q0 + warp * 16 + g;
    const int r1 = r0 + 8;
    const int lastjt_w = 2 * bx + (warp >= 4 ? 1 : 0);
    const int lastjt = 2 * bx + 1;

    #pragma unroll 1
    for (int s = 0; s < 2; ++s) {
        const int nb = s * 64;
        const float* ksrc = K + ((size_t)(b * T_ + nb + srow)) * E_ + h * 64 + scol;
        const float* vsrc = V + ((size_t)(b * T_ + nb + vrow)) * E_ + h * 64 + scol;
        uint32_t kd = sbase + (uint32_t)((s * FKBUF + srow * FKSTR + scol) * 4);
        uint32_t vd = vbase + (uint32_t)((s * FVBUF + srow * FVSTR + scol) * 4);
        #pragma unroll
        for (int u = 0; u < 4; ++u) {
            cp_async16(kd + u * 16, ksrc + u * 4);
            cp_async16(vd + u * 16, vsrc + u * 4);
        }
        cp_commit();
    }

    int sc = 0, sw = 2;
    for (int jt = 0; jt <= lastjt; ++jt) {
        cp_wait1();
        __syncthreads();

        if (jt + 2 <= lastjt) {
            const int n1 = (jt + 2) * 64;
            const float* ksrc = K + ((size_t)(b * T_ + n1 + srow)) * E_ + h * 64 + scol;
            const float* vsrc = V + ((size_t)(b * T_ + n1 + vrow)) * E_ + h * 64 + scol;
            uint32_t kd = sbase + (uint32_t)((sw * FKBUF + srow * FKSTR + scol) * 4);
            uint32_t vd = vbase + (uint32_t)((sw * FVBUF + srow * FVSTR + scol) * 4);
            #pragma unroll
            for (int u = 0; u < 4; ++u) {
                cp_async16(kd + u * 16, ksrc + u * 4);
                cp_async16(vd + u * 16, vsrc + u * 4);
            }
            cp_commit();
            if (++sw == 3) sw = 0;
        }

        if (jt <= lastjt_w) {
            const int n0 = jt * 64;
            const float* Kb = fsm + sc * FKBUF;
            const float* Vb = Vsm + sc * FVBUF;

            float sa[8][4];
            #pragma unroll
            for (int nt = 0; nt < 8; ++nt)
                #pragma unroll
                for (int r = 0; r < 4; ++r) sa[nt][r] = 0.0f;
            #pragma unroll
            for (int cc = 0; cc < 8; ++cc) {
                #pragma unroll
                for (int nt = 0; nt < 8; ++nt) {
                    float2 z = *(const float2*)(Kb + (nt * 8 + g) * FKSTR + cc * 8 + tg * 2);
                    mma_tf32(sa[nt], qf[cc][0], qf[cc][1], qf[cc][2], qf[cc][3],
                             __float_as_uint(z.x), __float_as_uint(z.y));
                }
            }

            float mx0 = -1e30f, mx1 = -1e30f;
            const bool diag = (jt == lastjt_w);
            #pragma unroll
            for (int nt = 0; nt < 8; ++nt) {
                int kc0 = n0 + nt * 8 + tg * 2;
                float a00 = slope * (float)(r0 - kc0);
                float a01 = a00 - slope;
                float a10 = slope * (float)(r1 - kc0);
                float a11 = a10 - slope;
                float v00 = fmaf(sa[nt][0], 0.125f, a00);
                float v01 = fmaf(sa[nt][1], 0.125f, a01);
                float v10 = fmaf(sa[nt][2], 0.125f, a10);
                float v11 = fmaf(sa[nt][3], 0.125f, a11);
                if (diag) {
                    if (kc0     > r0) v00 = -1e30f;
                    if (kc0 + 1 > r0) v01 = -1e30f;
                    if (kc0     > r1) v10 = -1e30f;
                    if (kc0 + 1 > r1) v11 = -1e30f;
                }
                sa[nt][0] = v00; sa[nt][1] = v01; sa[nt][2] = v10; sa[nt][3] = v11;
                mx0 = fmaxf(mx0, fmaxf(v00, v01));
                mx1 = fmaxf(mx1, fmaxf(v10, v11));
            }
            mx0 = fmaxf(mx0, __shfl_xor_sync(0xffffffffu, mx0, 1));
            mx0 = fmaxf(mx0, __shfl_xor_sync(0xffffffffu, mx0, 2));
            mx1 = fmaxf(mx1, __shfl_xor_sync(0xffffffffu, mx1, 1));
            mx1 = fmaxf(mx1, __shfl_xor_sync(0xffffffffu, mx1, 2));

            float mn0 = fmaxf(m0, mx0);
            float mn1 = fmaxf(m1, mx1);
            float sc0 = __expf(m0 - mn0);
            float sc1 = __expf(m1 - mn1);
            float rs0 = 0.0f, rs1 = 0.0f;
            #pragma unroll
            for (int nt = 0; nt < 8; ++nt) {
                float p00 = tf32f(__expf(sa[nt][0] - mn0));
                float p01 = tf32f(__expf(sa[nt][1] - mn0));
                float p10 = tf32f(__expf(sa[nt][2] - mn1));
                float p11 = tf32f(__expf(sa[nt][3] - mn1));
                rs0 += p00 + p01;
                rs1 += p10 + p11;
                sa[nt][0] = p00; sa[nt][1] = p01; sa[nt][2] = p10; sa[nt][3] = p11;
            }
            rs0 += __shfl_xor_sync(0xffffffffu, rs0, 1);
            rs0 += __shfl_xor_sync(0xffffffffu, rs0, 2);
            rs1 += __shfl_xor_sync(0xffffffffu, rs1, 1);
            rs1 += __shfl_xor_sync(0xffffffffu, rs1, 2);

            l0 = l0 * sc0 + rs0;
            l1 = l1 * sc1 + rs1;
            m0 = mn0; m1 = mn1;
            #pragma unroll
            for (int dt = 0; dt < 8; ++dt) {
                o[dt][0] *= sc0; o[dt][1] *= sc0;
                o[dt][2] *= sc1; o[dt][3] *= sc1;
            }

            // O += P @ V : C-fragment IS the A-fragment under key relabeling
            #pragma unroll
            for (int kc = 0; kc < 8; ++kc) {
                uint32_t a0 = __float_as_uint(sa[kc][0]);   // key 2tg,   row g
                uint32_t a1 = __float_as_uint(sa[kc][2]);   // key 2tg,   row g+8
                uint32_t a2 = __float_as_uint(sa[kc][1]);   // key 2tg+1, row g
                uint32_t a3 = __float_as_uint(sa[kc][3]);   // key 2tg+1, row g+8
                #pragma unroll
                for (int dt = 0; dt < 8; ++dt) {
                    uint32_t b0 = __float_as_uint(Vb[(kc * 8 + tg    ) * FVSTR + dt * 8 + g]);
                    uint32_t b1 = __float_as_uint(Vb[(kc * 8 + tg + 4) * FVSTR + dt * 8 + g]);
                    mma_tf32(o[dt], a0, a1, a2, a3, b0, b1);
                }
            }
        }
        if (++sc == 3) sc = 0;
    }

    // write attn into cat[:, 0:1024], tf32-rounded (row stride 2048)
    float il0 = 1.0f / l0, il1 = 1.0f / l1;
    #pragma unroll
    for (int dt = 0; dt < 8; ++dt) {
        float* d0 = O + ((size_t)(b * T_ + r0)) * (2 * E_) + h * 64 + dt * 8 + tg * 2;
        float* d1 = O + ((size_t)(b * T_ + r1)) * (2 * E_) + h * 64 + dt * 8 + tg * 2;
        *(float2*)d0 = make_float2(tf32f(o[dt][0] * il0), tf32f(o[dt][1] * il0));
        *(float2*)d1 = make_float2(tf32f(o[dt][2] * il1), tf32f(o[dt][3] * il1));
    }
}

// -------- merged hierarchy pooling --------
__global__ void pool_kernel(const float* __restrict__ Kf, const float* __restrict__ Vf,
                            float* __restrict__ K1, float* __restrict__ V1,
                            float* __restrict__ K2, float* __restrict__ V2) {
    int idx = blockIdx.x * blockDim.x + threadIdx.x;
    if (idx >= B_ * 32 * E_) return;
    int e = idx & (E_ - 1);
    int p = (idx >> 10) & 31;
    int b = idx >> 15;

    float k1a = 0.0f, v1a = 0.0f, k1b = 0.0f, v1b = 0.0f;
    {
        int t0 = (32 + 2 * p) * 16;
        #pragma unroll
        for (int u = 0; u < 16; ++u) {
            size_t off = ((size_t)(b * T_ + t0 + u) * E_) + e;
            k1a += Kf[off]; v1a += Vf[off];
        }
        t0 += 16;
        #pragma unroll
        for (int u = 0; u < 16; ++u) {
            size_t off = ((size_t)(b * T_ + t0 + u) * E_) + e;
            k1b += Kf[off]; v1b += Vf[off];
        }
    }
    k1a *= (1.0f / 16.0f); v1a *= (1.0f / 16.0f);
    k1b *= (1.0f / 16.0f); v1b *= (1.0f / 16.0f);

    size_t o1 = ((size_t)(b * 64 + 2 * p)) * E_ + e;
    K1[o1] = k1a;        V1[o1] = v1a;
    K1[o1 + E_] = k1b;   V1[o1 + E_] = v1b;

    K2[idx] = 0.5f * (k1a + k1b);
    V2[idx] = 0.5f * (v1a + v1b);
}

// ============ hierarchical attention (dots invariant: qh & K1 both permuted) ============
__global__ void __launch_bounds__(128)
hier_attn_kernel(const float* __restrict__ Qh,
                 const float* __restrict__ K1, const float* __restrict__ V1,
                 const float* __restrict__ K2, const float* __restrict__ V2,
                 const float* __restrict__ gate,
                 float* __restrict__ cat) {
    __shared__ float Qs[32][65];
    __shared__ float KV[96][68];
    __shared__ float Ss[32][97];

    const int bh = blockIdx.y;
    const int b = bh >> 4;
    const int h = bh & 15;
    const int t0 = blockIdx.x * 32;
    const int tid = threadIdx.x;
    const int q = tid >> 2;
    const int qt = tid & 3;
    const int qc = qt * 16;

    const float gsig = 1.0f / (1.0f + __expf(-__ldg(gate)));

    for (int i = tid; i < 32 * 16; i += 128) {
        int r = i >> 4, c4 = (i & 15) << 2;
        float4 v = *(const float4*)(Qh + ((size_t)(b * T_ + t0 + r)) * E_ + h * 64 + c4);
        Qs[r][c4] = v.x; Qs[r][c4 + 1] = v.y; Qs[r][c4 + 2] = v.z; Qs[r][c4 + 3] = v.w;
    }
    for (int i = tid; i < 96 * 16; i += 128) {
        int r = i >> 4, c4 = (i & 15) << 2;
        const float* src = (r < 64)
            ? (K1 + ((size_t)(b * 64 + r)) * E_ + h * 64 + c4)
            : (K2 + ((size_t)(b * 32 + r - 64)) * E_ + h * 64 + c4);
        *(float4*)&KV[r][c4] = *(const float4*)src;
    }
    __syncthreads();

    for (int m = 0; m < 96; ++m) {
        float s = 0.0f;
        #pragma unroll
        for (int d = 0; d < 16; ++d)
            s = fmaf(Qs[q][qc + d], KV[m][qc + d], s);
        s += __shfl_xor_sync(0xffffffffu, s, 1);
        s += __shfl_xor_sync(0xffffffffu, s, 2);
        if (qt == 0) Ss[q][m] = s * 0.125f;
    }
    __syncthreads();

    for (int i = tid; i < 96 * 16; i += 128) {
        int r = i >> 4, c4 = (i & 15) << 2;
        const float* src = (r < 64)
            ? (V1 + ((size_t)(b * 64 + r)) * E_ + h * 64 + c4)
            : (V2 + ((size_t)(b * 32 + r - 64)) * E_ + h * 64 + c4);
        *(float4*)&KV[r][c4] = *(const float4*)src;
    }
    __syncthreads();

    float mx1 = -1e30f;
    for (int m = 0; m < 64; ++m) mx1 = fmaxf(mx1, Ss[q][m]);
    float o1[16];
    #pragma unroll
    for (int d = 0; d < 16; ++d) o1[d] = 0.0f;
    float sum1 = 0.0f;
    for (int m = 0; m < 64; ++m) {
        float p = __expf(Ss[q][m] - mx1);
        sum1 += p;
        #pragma unroll
        for (int d = 0; d < 16; ++d) o1[d] = fmaf(p, KV[m][qc + d], o1[d]);
    }
    float mx2 = -1e30f;
    for (int m = 64; m < 96; ++m) mx2 = fmaxf(mx2, Ss[q][m]);
    float o2[16];
    #pragma unroll
    for (int d = 0; d < 16; ++d) o2[d] = 0.0f;
    float sum2 = 0.0f;
    for (int m = 64; m < 96; ++m) {
        float p = __expf(Ss[q][m] - mx2);
        sum2 += p;
        #pragma unroll
        for (int d = 0; d < 16; ++d) o2[d] = fmaf(p, KV[m][qc + d], o2[d]);
    }
    float inv1 = gsig / sum1, inv2 = gsig / sum2;

    float* dst = cat + ((size_t)(b * T_ + t0 + q)) * (2 * E_) + E_ + h * 64 + qc;
    #pragma unroll
    for (int d4 = 0; d4 < 16; d4 += 4) {
        *(float4*)(dst + d4) = make_float4(
            tf32f(o1[d4 + 0] * inv1 + o2[d4 + 0] * inv2),
            tf32f(o1[d4 + 1] * inv1 + o2[d4 + 1] * inv2),
            tf32f(o1[d4 + 2] * inv1 + o2[d4 + 2] * inv2),
            tf32f(o1[d4 + 3] * inv1 + o2[d4 + 3] * inv2));
    }
}

__global__ void zero_tail_kernel(float* p, int n) {
    int i = blockIdx.x * blockDim.x + threadIdx.x;
    if (i < n) p[i] = 0.0f;
}

// -------- launch --------
extern "C" void kernel_launch(void* const* d_in, const int* in_sizes, int n_in,
                              void* d_out, int out_size) {
    const float* x      = (const float*)d_in[0];
    const float* Wq_w   = (const float*)d_in[1];
    const float* Wq_A   = (const float*)d_in[2];
    const float* Wq_B   = (const float*)d_in[3];
    const float* Wk_w   = (const float*)d_in[4];
    const float* Wk_A   = (const float*)d_in[5];
    const float* Wk_B   = (const float*)d_in[6];
    const float* Wv_w   = (const float*)d_in[7];
    const float* Wv_A   = (const float*)d_in[8];
    const float* Wv_B   = (const float*)d_in[9];
    const float* proj_w = (const float*)d_in[10];
    const float* hq_w   = (const float*)d_in[11];
    const float* hp_w   = (const float*)d_in[12];
    const float* gate   = (const float*)d_in[13];
    const float* slopes = (const float*)d_in[14];
    float* out = (float*)d_out;

    float *wall, *wcat, *xr, *q, *k, *v, *qh, *cat, *K1, *V1, *K2, *V2;
    cudaGetSymbolAddress((void**)&wall, g_Wall);
    cudaGetSymbolAddress((void**)&wcat, g_Wcat);
    cudaGetSymbolAddress((void**)&xr, g_xr);
    cudaGetSymbolAddress((void**)&q, g_q);
    cudaGetSymbolAddress((void**)&k, g_k);
    cudaGetSymbolAddress((void**)&v, g_v);
    cudaGetSymbolAddress((void**)&qh, g_qh);
    cudaGetSymbolAddress((void**)&cat, g_cat);
    cudaGetSymbolAddress((void**)&K1, g_K1);
    cudaGetSymbolAddress((void**)&V1, g_V1);
    cudaGetSymbolAddress((void**)&K2, g_K2);
    cudaGetSymbolAddress((void**)&V2, g_V2);

    cudaFuncSetAttribute(gemm_tf32_nt_kernel,
                         cudaFuncAttributeMaxDynamicSharedMemorySize, GEMM_SMEM_BYTES);
    cudaFuncSetAttribute(flash_tf32_kernel,
                         cudaFuncAttributeMaxDynamicSharedMemorySize, FLASH_SMEM_BYTES);

    // 1. pre-round inputs; wq/wk/hq rows permuted (pairs-adjacent d)
    fold_lora_kernel<<<(E_ * E_) / 256, 256>>>(Wq_w, Wq_A, Wq_B, wall, 1);
    fold_lora_kernel<<<(E_ * E_) / 256, 256>>>(Wk_w, Wk_A, Wk_B, wall + E_ * E_, 1);
    fold_lora_kernel<<<(E_ * E_) / 256, 256>>>(Wv_w, Wv_A, Wv_B, wall + 2 * E_ * E_, 0);
    round_permrow_kernel<<<(E_ * E_ / 4) / 256, 256>>>(hq_w, wall + 3 * E_ * E_);
    round_tf32_kernel<<<(BTE_ / 4) / 256, 256>>>(x, xr);

    // 2. merged projection GEMM
    gemm_tf32_nt_kernel<<<dim3(32, BT_ / GBM), 256, GEMM_SMEM_BYTES>>>(
        xr, wall, q, k, v, qh, E_, 1);

    // 3. causal attention with alibi -> cat[:, 0:1024]
    flash_tf32_kernel<<<dim3(T_ / 128, B_ * H_), 256, FLASH_SMEM_BYTES>>>(
        q, k, v, slopes, cat);

    // 4. merged hierarchy pooling + small attention -> cat[:, 1024:2048]
    pool_kernel<<<(B_ * 32 * E_ + 255) / 256, 256>>>(k, v, K1, V1, K2, V2);
    hier_attn_kernel<<<dim3(T_ / 32, B_ * H_), 128>>>(qh, K1, V1, K2, V2, gate, cat);

    // 5. pack epilogue weights and ONE merged epilogue GEMM (K = 2048)
    pack_weights_kernel<<<(E_ * E_ / 4) / 256, 256>>>(proj_w, hp_w, wcat);
    gemm_tf32_nt_kernel<<<dim3(8, BT_ / GBM), 256, GEMM_SMEM_BYTES>>>(
        cat, wcat, out, out, out, out, 2 * E_, 0);

    // 6. recon output is exactly zero
    if (out_size > BTE_) {
        int tail = out_size - BTE_;
        zero_tail_kernel<<<(tail + 255) / 256, 256>>>(out + BTE_, tail);
    }
}

// round 16
// speedup vs baseline: 1.0211x; 1.0002x over previous
#include <cuda_runtime.h>
#include <math.h>
#include <stdint.h>

#define B_  4
#define T_  2048
#define E_  1024
#define H_  16
#define DH_ 64
#define BT_ (B_*T_)
#define BTE_ (B_*T_*E_)
#define LOG2E_ 1.4426950408889634f

// -------- scratch (device globals; no allocation allowed) --------
__device__ float g_Wall[4*E_*E_];     // folded+rounded wq* | wk* | wv | hq*  (* = row-permuted)
__device__ float g_Wcat[2*E_*E_];     // packed+rounded [proj|hp], rows of 2048
__device__ float g_xr[BTE_];          // tf32-rounded x
__device__ float g_q[BTE_];           // d-permuted (pairs adjacent)
__device__ float g_k[BTE_];           // d-permuted
__device__ float g_v[BTE_];           // NOT permuted
__device__ float g_qh[BTE_];          // d-permuted
__device__ float g_cat[BT_*2*E_];     // [attn | gate*ctx], rows of 2048
__device__ float g_K1[B_*64*E_];
__device__ float g_V1[B_*64*E_];
__device__ float g_K2[B_*32*E_];
__device__ float g_V2[B_*32*E_];

// -------- helpers --------
__device__ __forceinline__ uint32_t tf32u(float x) {
    uint32_t u;
    asm("cvt.rna.tf32.f32 %0, %1;" : "=r"(u) : "f"(x));
    return u;
}
__device__ __forceinline__ float tf32f(float x) { return __uint_as_float(tf32u(x)); }

// pair-permutation within 8-groups: j -> 2*(j&3) + (j>>2)
__device__ __forceinline__ int cperm(int n) {
    return (n & ~7) | (((n & 3) << 1) | ((n >> 2) & 1));
}

__device__ __forceinline__ void mma_tf32(float* c,
                                         uint32_t a0, uint32_t a1, uint32_t a2, uint32_t a3,
                                         uint32_t b0, uint32_t b1) {
    asm volatile(
        "mma.sync.aligned.m16n8k8.row.col.f32.tf32.tf32.f32 "
        "{%0,%1,%2,%3},{%4,%5,%6,%7},{%8,%9},{%0,%1,%2,%3};"
        : "+f"(c[0]), "+f"(c[1]), "+f"(c[2]), "+f"(c[3])
        : "r"(a0), "r"(a1), "r"(a2), "r"(a3), "r"(b0), "r"(b1));
}

__device__ __forceinline__ void cp_async16(uint32_t smem_addr, const void* gptr) {
    asm volatile("cp.async.cg.shared.global [%0], [%1], 16;\n"
                 :: "r"(smem_addr), "l"(gptr));
}
__device__ __forceinline__ void cp_commit() {
    asm volatile("cp.async.commit_group;\n");
}
__device__ __forceinline__ void cp_wait1() {
    asm volatile("cp.async.wait_group 1;\n");
}

// -------- fold LoRA (tf32-rounded); optional row permutation --------
__global__ void fold_lora_kernel(const float* __restrict__ W,
                                 const float* __restrict__ A,
                                 const float* __restrict__ Bm,
                                 float* __restrict__ Weff, int permute) {
    int idx = blockIdx.x * blockDim.x + threadIdx.x;
    int n = idx >> 10;
    int k = idx & 1023;
    float acc = W[idx];
    #pragma unroll
    for (int r = 0; r < 8; ++r)
        acc += 2.0f * A[n * 8 + r] * Bm[r * E_ + k];
    int nd = permute ? cperm(n) : n;
    Weff[(size_t)nd * E_ + k] = tf32f(acc);
}

// -------- elementwise tf32 rounding --------
__global__ void round_tf32_kernel(const float* __restrict__ src, float* __restrict__ dst) {
    int i = blockIdx.x * blockDim.x + threadIdx.x;
    float4 v = ((const float4*)src)[i];
    ((float4*)dst)[i] = make_float4(tf32f(v.x), tf32f(v.y), tf32f(v.z), tf32f(v.w));
}

// -------- round + row-permute (for hq) --------
__global__ void round_permrow_kernel(const float* __restrict__ src, float* __restrict__ dst) {
    int i = blockIdx.x * blockDim.x + threadIdx.x;
    int n = i >> 8;
    int kq = (i & 255) << 2;
    float4 v = *(const float4*)(src + (size_t)n * E_ + kq);
    *(float4*)(dst + (size_t)cperm(n) * E_ + kq) =
        make_float4(tf32f(v.x), tf32f(v.y), tf32f(v.z), tf32f(v.w));
}

// -------- pack epilogue weights --------
__global__ void pack_weights_kernel(const float* __restrict__ proj,
                                    const float* __restrict__ hp,
                                    float* __restrict__ Wcat) {
    int i = blockIdx.x * blockDim.x + threadIdx.x;
    int n = i >> 8;
    int kq = (i & 255) << 2;
    float4 p = *(const float4*)(proj + (size_t)n * E_ + kq);
    float4 h = *(const float4*)(hp   + (size_t)n * E_ + kq);
    *(float4*)(Wcat + (size_t)n * 2 * E_ + kq) =
        make_float4(tf32f(p.x), tf32f(p.y), tf32f(p.z), tf32f(p.w));
    *(float4*)(Wcat + (size_t)n * 2 * E_ + E_ + kq) =
        make_float4(tf32f(h.x), tf32f(h.y), tf32f(h.z), tf32f(h.w));
}

// ====== tf32 GEMM: 3-stage cp.async pipeline (unchanged hot loop) ======
#define GBM 128
#define GBK 32
#define GST 36
#define GBUF_FLOATS (128*GST)
#define GBUF_BYTES  (GBUF_FLOATS*4)
#define GEMM_SMEM_BYTES (6*GBUF_BYTES)   // 110592

__global__ void __launch_bounds__(256, 2)
gemm_tf32_nt_kernel(const float* __restrict__ A, const float* __restrict__ Bmat,
                    float* __restrict__ C0, float* __restrict__ C1,
                    float* __restrict__ C2, float* __restrict__ C3,
                    int K, int round_out) {
    extern __shared__ float sm[];
    const uint32_t sbase = (uint32_t)__cvta_generic_to_shared(sm);
    const uint32_t bbase = sbase + 3u * GBUF_BYTES;

    const int tid  = threadIdx.x;
    const int warp = tid >> 5;
    const int lane = tid & 31;
    const int wm = warp >> 2;
    const int wn = warp & 3;
    const int g  = lane >> 2;
    const int tg = lane & 3;

    const int bm = blockIdx.y * GBM;
    const int cb = blockIdx.x;
    const int bnW = cb * 128;
    float* Cbuf = (cb < 8) ? C0 : (cb < 16) ? C1 : (cb < 24) ? C2 : C3;
    const int bnC = (cb & 7) * 128;

    float c[4][4][4];
    #pragma unroll
    for (int i = 0; i < 4; ++i)
        #pragma unroll
        for (int j = 0; j < 4; ++j)
            #pragma unroll
            for (int r = 0; r < 4; ++r) c[i][j][r] = 0.0f;

    int lm[4], lkq[4];
    #pragma unroll
    for (int u = 0; u < 4; ++u) {
        int lin = tid + u * 256;
        lm[u]  = lin >> 3;
        lkq[u] = (lin & 7) << 2;
    }

    const int NT = K / GBK;

    #pragma unroll 1
    for (int s = 0; s < 2; ++s) {
        const int kb = s * GBK;
        const uint32_t off = (uint32_t)(s * GBUF_BYTES);
        #pragma unroll
        for (int u = 0; u < 4; ++u) {
            uint32_t da = sbase + off + (uint32_t)(lm[u] * 144 + lkq[u] * 4);
            uint32_t db = bbase + off + (uint32_t)(lm[u] * 144 + lkq[u] * 4);
            cp_async16(da, A    + (size_t)(bm  + lm[u]) * K + kb + lkq[u]);
            cp_async16(db, Bmat + (size_t)(bnW + lm[u]) * K + kb + lkq[u]);
        }
        cp_commit();
    }

    int sc = 0, sw = 2;
    for (int kt = 0; kt < NT; ++kt) {
        cp_wait1();
        __syncthreads();

        if (kt + 2 < NT) {
            const int kb = (kt + 2) * GBK;
            const uint32_t off = (uint32_t)(sw * GBUF_BYTES);
            #pragma unroll
            for (int u = 0; u < 4; ++u) {
                uint32_t da = sbase + off + (uint32_t)(lm[u] * 144 + lkq[u] * 4);
                uint32_t db = bbase + off + (uint32_t)(lm[u] * 144 + lkq[u] * 4);
                cp_async16(da, A    + (size_t)(bm  + lm[u]) * K + kb + lkq[u]);
                cp_async16(db, Bmat + (size_t)(bnW + lm[u]) * K + kb + lkq[u]);
            }
            cp_commit();
            if (++sw == 3) sw = 0;
        }

        const float* Ab = sm + sc * GBUF_FLOATS;
        const float* Bb = sm + 3 * GBUF_FLOATS + sc * GBUF_FLOATS;
        #pragma unroll
        for (int ks = 0; ks < GBK; ks += 8) {
            uint32_t af[4][4], bf[4][2];
            #pragma unroll
            for (int mt = 0; mt < 4; ++mt) {
                int m = wm * 64 + mt * 16;
                af[mt][0] = __float_as_uint(Ab[(m + g    ) * GST + ks + tg    ]);
                af[mt][1] = __float_as_uint(Ab[(m + g + 8) * GST + ks + tg    ]);
                af[mt][2] = __float_as_uint(Ab[(m + g    ) * GST + ks + tg + 4]);
                af[mt][3] = __float_as_uint(Ab[(m + g + 8) * GST + ks + tg + 4]);
            }
            #pragma unroll
            for (int nt = 0; nt < 4; ++nt) {
                int n = wn * 32 + nt * 8;
                bf[nt][0] = __float_as_uint(Bb[(n + g) * GST + ks + tg    ]);
                bf[nt][1] = __float_as_uint(Bb[(n + g) * GST + ks + tg + 4]);
            }
            #pragma unroll
            for (int mt = 0; mt < 4; ++mt)
                #pragma unroll
                for (int nt = 0; nt < 4; ++nt)
                    mma_tf32(c[mt][nt], af[mt][0], af[mt][1], af[mt][2], af[mt][3],
                             bf[nt][0], bf[nt][1]);
        }
        if (++sc == 3) sc = 0;
    }

    #pragma unroll
    for (int mt = 0; mt < 4; ++mt) {
        #pragma unroll
        for (int nt = 0; nt < 4; ++nt) {
            int row0 = bm + wm * 64 + mt * 16 + g;
            int col  = bnC + wn * 32 + nt * 8 + tg * 2;
            float* p0 = Cbuf + (size_t)row0 * E_ + col;
            float* p1 = Cbuf + (size_t)(row0 + 8) * E_ + col;
            float v0 = c[mt][nt][0];
            float v1 = c[mt][nt][1];
            float v2 = c[mt][nt][2];
            float v3 = c[mt][nt][3];
            if (round_out) { v0 = tf32f(v0); v1 = tf32f(v1); v2 = tf32f(v2); v3 = tf32f(v3); }
            p0[0] = v0; p0[1] = v1; p1[0] = v2; p1[1] = v3;
        }
    }
}

// ====== flash attention: key-relabeled V, log2-domain softmax ======
#define FKSTR 72
#define FVSTR 72
#define FKBUF (64*FKSTR)
#define FVBUF (64*FVSTR)
#define FLASH_SMEM_BYTES (3*(FKBUF+FVBUF)*4)   // 110592

__global__ void __launch_bounds__(256, 2)
flash_tf32_kernel(const float* __restrict__ Q, const float* __restrict__ K,
                  const float* __restrict__ V, const float* __restrict__ slopes,
                  float* __restrict__ O) {
    extern __shared__ float fsm[];
    const uint32_t sbase = (uint32_t)__cvta_generic_to_shared(fsm);
    const uint32_t vbase = sbase + 3u * FKBUF * 4u;
    float* Vsm = fsm + 3 * FKBUF;

    const int bh = blockIdx.y;
    const int b = bh >> 4;
    const int h = bh & 15;
    const int bx = (int)gridDim.x - 1 - (int)blockIdx.x;   // heavy blocks first
    const int q0 = bx * 128;
    const int tid = threadIdx.x;
    const int warp = tid >> 5;
    const int lane = tid & 31;
    const int g = lane >> 2;
    const int tg = lane & 3;
    // log2-domain constants: s*0.125 + slope*(i-j)  ==>  multiply all by log2(e)
    const float SCL2 = 0.125f * LOG2E_;
    const float slope2 = slopes[h] * LOG2E_;

    const int srow = tid >> 2;
    const int scol = (tid & 3) * 16;
    const int vrow = (srow & ~7) | (((srow & 3) << 1) | ((srow >> 2) & 1));

    // ---- stage Q halves (d-permuted), pick fragments as LDS.64 pairs ----
    uint32_t qf[8][4];
    #pragma unroll 1
    for (int half = 0; half < 2; ++half) {
        const float* src = Q + ((size_t)(b * T_ + q0 + half * 64 + srow)) * E_ + h * 64 + scol;
        #pragma unroll
        for (int u = 0; u < 4; ++u)
            *(float4*)&fsm[srow * FKSTR + scol + u * 4] = *(const float4*)(src + u * 4);
        __syncthreads();
        if ((warp >> 2) == half) {
            int lr = (warp & 3) * 16;
            #pragma unroll
            for (int cc = 0; cc < 8; ++cc) {
                float2 x = *(const float2*)&fsm[(lr + g    ) * FKSTR + cc * 8 + tg * 2];
                float2 y = *(const float2*)&fsm[(lr + g + 8) * FKSTR + cc * 8 + tg * 2];
                qf[cc][0] = __float_as_uint(x.x);
                qf[cc][2] = __float_as_uint(x.y);
                qf[cc][1] = __float_as_uint(y.x);
                qf[cc][3] = __float_as_uint(y.y);
            }
        }
        __syncthreads();
    }

    float o[8][4];
    #pragma unroll
    for (int dt = 0; dt < 8; ++dt)
        #pragma unroll
        for (int r = 0; r < 4; ++r) o[dt][r] = 0.0f;

    float m0 = -1e30f, m1 = -1e30f, l0 = 0.0f, l1 = 0.0f;
    const int r0 = q0 + warp * 16 + g;
    const int r1 = r0 + 8;
    const int lastjt_w = 2 * bx + (warp >= 4 ? 1 : 0);
    const int lastjt = 2 * bx + 1;

    #pragma unroll 1
    for (int s = 0; s < 2; ++s) {
        const int nb = s * 64;
        const float* ksrc = K + ((size_t)(b * T_ + nb + srow)) * E_ + h * 64 + scol;
        const float* vsrc = V + ((size_t)(b * T_ + nb + vrow)) * E_ + h * 64 + scol;
        uint32_t kd = sbase + (uint32_t)((s * FKBUF + srow * FKSTR + scol) * 4);
        uint32_t vd = vbase + (uint32_t)((s * FVBUF + srow * FVSTR + scol) * 4);
        #pragma unroll
        for (int u = 0; u < 4; ++u) {
            cp_async16(kd + u * 16, ksrc + u * 4);
            cp_async16(vd + u * 16, vsrc + u * 4);
        }
        cp_commit();
    }

    int sc = 0, sw = 2;
    for (int jt = 0; jt <= lastjt; ++jt) {
        cp_wait1();
        __syncthreads();

        if (jt + 2 <= lastjt) {
            const int n1 = (jt + 2) * 64;
            const float* ksrc = K + ((size_t)(b * T_ + n1 + srow)) * E_ + h * 64 + scol;
            const float* vsrc = V + ((size_t)(b * T_ + n1 + vrow)) * E_ + h * 64 + scol;
            uint32_t kd = sbase + (uint32_t)((sw * FKBUF + srow * FKSTR + scol) * 4);
            uint32_t vd = vbase + (uint32_t)((sw * FVBUF + srow * FVSTR + scol) * 4);
            #pragma unroll
            for (int u = 0; u < 4; ++u) {
                cp_async16(kd + u * 16, ksrc + u * 4);
                cp_async16(vd + u * 16, vsrc + u * 4);
            }
            cp_commit();
            if (++sw == 3) sw = 0;
        }

        if (jt <= lastjt_w) {
            const int n0 = jt * 64;
            const float* Kb = fsm + sc * FKBUF;
            const float* Vb = Vsm + sc * FVBUF;

            float sa[8][4];
            #pragma unroll
            for (int nt = 0; nt < 8; ++nt)
                #pragma unroll
                for (int r = 0; r < 4; ++r) sa[nt][r] = 0.0f;
            #pragma unroll
            for (int cc = 0; cc < 8; ++cc) {
                #pragma unroll
                for (int nt = 0; nt < 8; ++nt) {
                    float2 z = *(const float2*)(Kb + (nt * 8 + g) * FKSTR + cc * 8 + tg * 2);
                    mma_tf32(sa[nt], qf[cc][0], qf[cc][1], qf[cc][2], qf[cc][3],
                             __float_as_uint(z.x), __float_as_uint(z.y));
                }
            }

            float mx0 = -1e30f, mx1 = -1e30f;
            const bool diag = (jt == lastjt_w);
            #pragma unroll
            for (int nt = 0; nt < 8; ++nt) {
                int kc0 = n0 + nt * 8 + tg * 2;
                float a00 = slope2 * (float)(r0 - kc0);
                float a01 = a00 - slope2;
                float a10 = slope2 * (float)(r1 - kc0);
                float a11 = a10 - slope2;
                float v00 = fmaf(sa[nt][0], SCL2, a00);
                float v01 = fmaf(sa[nt][1], SCL2, a01);
                float v10 = fmaf(sa[nt][2], SCL2, a10);
                float v11 = fmaf(sa[nt][3], SCL2, a11);
                if (diag) {
                    if (kc0     > r0) v00 = -1e30f;
                    if (kc0 + 1 > r0) v01 = -1e30f;
                    if (kc0     > r1) v10 = -1e30f;
                    if (kc0 + 1 > r1) v11 = -1e30f;
                }
                sa[nt][0] = v00; sa[nt][1] = v01; sa[nt][2] = v10; sa[nt][3] = v11;
                mx0 = fmaxf(mx0, fmaxf(v00, v01));
                mx1 = fmaxf(mx1, fmaxf(v10, v11));
            }
            mx0 = fmaxf(mx0, __shfl_xor_sync(0xffffffffu, mx0, 1));
            mx0 = fmaxf(mx0, __shfl_xor_sync(0xffffffffu, mx0, 2));
            mx1 = fmaxf(mx1, __shfl_xor_sync(0xffffffffu, mx1, 1));
            mx1 = fmaxf(mx1, __shfl_xor_sync(0xffffffffu, mx1, 2));

            float mn0 = fmaxf(m0, mx0);
            float mn1 = fmaxf(m1, mx1);
            float sc0 = exp2f(m0 - mn0);
            float sc1 = exp2f(m1 - mn1);
            float rs0 = 0.0f, rs1 = 0.0f;
            #pragma unroll
            for (int nt = 0; nt < 8; ++nt) {
                float p00 = tf32f(exp2f(sa[nt][0] - mn0));
                float p01 = tf32f(exp2f(sa[nt][1] - mn0));
                float p10 = tf32f(exp2f(sa[nt][2] - mn1));
                float p11 = tf32f(exp2f(sa[nt][3] - mn1));
                rs0 += p00 + p01;
                rs1 += p10 + p11;
                sa[nt][0] = p00; sa[nt][1] = p01; sa[nt][2] = p10; sa[nt][3] = p11;
            }
            rs0 += __shfl_xor_sync(0xffffffffu, rs0, 1);
            rs0 += __shfl_xor_sync(0xffffffffu, rs0, 2);
            rs1 += __shfl_xor_sync(0xffffffffu, rs1, 1);
            rs1 += __shfl_xor_sync(0xffffffffu, rs1, 2);

            l0 = l0 * sc0 + rs0;
            l1 = l1 * sc1 + rs1;
            m0 = mn0; m1 = mn1;
            #pragma unroll
            for (int dt = 0; dt < 8; ++dt) {
                o[dt][0] *= sc0; o[dt][1] *= sc0;
                o[dt][2] *= sc1; o[dt][3] *= sc1;
            }

            // O += P @ V : C-fragment IS the A-fragment under key relabeling
            #pragma unroll
            for (int kc = 0; kc < 8; ++kc) {
                uint32_t a0 = __float_as_uint(sa[kc][0]);
                uint32_t a1 = __float_as_uint(sa[kc][2]);
                uint32_t a2 = __float_as_uint(sa[kc][1]);
                uint32_t a3 = __float_as_uint(sa[kc][3]);
                #pragma unroll
                for (int dt = 0; dt < 8; ++dt) {
                    uint32_t b0 = __float_as_uint(Vb[(kc * 8 + tg    ) * FVSTR + dt * 8 + g]);
                    uint32_t b1 = __float_as_uint(Vb[(kc * 8 + tg + 4) * FVSTR + dt * 8 + g]);
                    mma_tf32(o[dt], a0, a1, a2, a3, b0, b1);
                }
            }
        }
        if (++sc == 3) sc = 0;
    }

    // write attn into cat[:, 0:1024], tf32-rounded (row stride 2048)
    float il0 = 1.0f / l0, il1 = 1.0f / l1;
    #pragma unroll
    for (int dt = 0; dt < 8; ++dt) {
        float* d0 = O + ((size_t)(b * T_ + r0)) * (2 * E_) + h * 64 + dt * 8 + tg * 2;
        float* d1 = O + ((size_t)(b * T_ + r1)) * (2 * E_) + h * 64 + dt * 8 + tg * 2;
        *(float2*)d0 = make_float2(tf32f(o[dt][0] * il0), tf32f(o[dt][1] * il0));
        *(float2*)d1 = make_float2(tf32f(o[dt][2] * il1), tf32f(o[dt][3] * il1));
    }
}

// -------- merged hierarchy pooling --------
__global__ void pool_kernel(const float* __restrict__ Kf, const float* __restrict__ Vf,
                            float* __restrict__ K1, float* __restrict__ V1,
                            float* __restrict__ K2, float* __restrict__ V2) {
    int idx = blockIdx.x * blockDim.x + threadIdx.x;
    if (idx >= B_ * 32 * E_) return;
    int e = idx & (E_ - 1);
    int p = (idx >> 10) & 31;
    int b = idx >> 15;

    float k1a = 0.0f, v1a = 0.0f, k1b = 0.0f, v1b = 0.0f;
    {
        int t0 = (32 + 2 * p) * 16;
        #pragma unroll
        for (int u = 0; u < 16; ++u) {
            size_t off = ((size_t)(b * T_ + t0 + u) * E_) + e;
            k1a += Kf[off]; v1a += Vf[off];
        }
        t0 += 16;
        #pragma unroll
        for (int u = 0; u < 16; ++u) {
            size_t off = ((size_t)(b * T_ + t0 + u) * E_) + e;
            k1b += Kf[off]; v1b += Vf[off];
        }
    }
    k1a *= (1.0f / 16.0f); v1a *= (1.0f / 16.0f);
    k1b *= (1.0f / 16.0f); v1b *= (1.0f / 16.0f);

    size_t o1 = ((size_t)(b * 64 + 2 * p)) * E_ + e;
    K1[o1] = k1a;        V1[o1] = v1a;
    K1[o1 + E_] = k1b;   V1[o1 + E_] = v1b;

    K2[idx] = 0.5f * (k1a + k1b);
    V2[idx] = 0.5f * (v1a + v1b);
}

// ============ hierarchical attention (log2-domain softmax) ============
__global__ void __launch_bounds__(128)
hier_attn_kernel(const float* __restrict__ Qh,
                 const float* __restrict__ K1, const float* __restrict__ V1,
                 const float* __restrict__ K2, const float* __restrict__ V2,
                 const float* __restrict__ gate,
                 float* __restrict__ cat) {
    __shared__ float Qs[32][65];
    __shared__ float KV[96][68];
    __shared__ float Ss[32][97];

    const int bh = blockIdx.y;
    const int b = bh >> 4;
    const int h = bh & 15;
    const int t0 = blockIdx.x * 32;
    const int tid = threadIdx.x;
    const int q = tid >> 2;
    const int qt = tid & 3;
    const int qc = qt * 16;
    const float SCL2 = 0.125f * LOG2E_;

    const float gsig = 1.0f / (1.0f + __expf(-__ldg(gate)));

    for (int i = tid; i < 32 * 16; i += 128) {
        int r = i >> 4, c4 = (i & 15) << 2;
        float4 v = *(const float4*)(Qh + ((size_t)(b * T_ + t0 + r)) * E_ + h * 64 + c4);
        Qs[r][c4] = v.x; Qs[r][c4 + 1] = v.y; Qs[r][c4 + 2] = v.z; Qs[r][c4 + 3] = v.w;
    }
    for (int i = tid; i < 96 * 16; i += 128) {
        int r = i >> 4, c4 = (i & 15) << 2;
        const float* src = (r < 64)
            ? (K1 + ((size_t)(b * 64 + r)) * E_ + h * 64 + c4)
            : (K2 + ((size_t)(b * 32 + r - 64)) * E_ + h * 64 + c4);
        *(float4*)&KV[r][c4] = *(const float4*)src;
    }
    __syncthreads();

    for (int m = 0; m < 96; ++m) {
        float s = 0.0f;
        #pragma unroll
        for (int d = 0; d < 16; ++d)
            s = fmaf(Qs[q][qc + d], KV[m][qc + d], s);
        s += __shfl_xor_sync(0xffffffffu, s, 1);
        s += __shfl_xor_sync(0xffffffffu, s, 2);
        if (qt == 0) Ss[q][m] = s * SCL2;
    }
    __syncthreads();

    for (int i = tid; i < 96 * 16; i += 128) {
        int r = i >> 4, c4 = (i & 15) << 2;
        const float* src = (r < 64)
            ? (V1 + ((size_t)(b * 64 + r)) * E_ + h * 64 + c4)
            : (V2 + ((size_t)(b * 32 + r - 64)) * E_ + h * 64 + c4);
        *(float4*)&KV[r][c4] = *(const float4*)src;
    }
    __syncthreads();

    float mx1 = -1e30f;
    for (int m = 0; m < 64; ++m) mx1 = fmaxf(mx1, Ss[q][m]);
    float o1[16];
    #pragma unroll
    for (int d = 0; d < 16; ++d) o1[d] = 0.0f;
    float sum1 = 0.0f;
    for (int m = 0; m < 64; ++m) {
        float p = exp2f(Ss[q][m] - mx1);
        sum1 += p;
        #pragma unroll
        for (int d = 0; d < 16; ++d) o1[d] = fmaf(p, KV[m][qc + d], o1[d]);
    }
    float mx2 = -1e30f;
    for (int m = 64; m < 96; ++m) mx2 = fmaxf(mx2, Ss[q][m]);
    float o2[16];
    #pragma unroll
    for (int d = 0; d < 16; ++d) o2[d] = 0.0f;
    float sum2 = 0.0f;
    for (int m = 64; m < 96; ++m) {
        float p = exp2f(Ss[q][m] - mx2);
        sum2 += p;
        #pragma unroll
        for (int d = 0; d < 16; ++d) o2[d] = fmaf(p, KV[m][qc + d], o2[d]);
    }
    float inv1 = gsig / sum1, inv2 = gsig / sum2;

    float* dst = cat + ((size_t)(b * T_ + t0 + q)) * (2 * E_) + E_ + h * 64 + qc;
    #pragma unroll
    for (int d4 = 0; d4 < 16; d4 += 4) {
        *(float4*)(dst + d4) = make_float4(
            tf32f(o1[d4 + 0] * inv1 + o2[d4 + 0] * inv2),
            tf32f(o1[d4 + 1] * inv1 + o2[d4 + 1] * inv2),
            tf32f(o1[d4 + 2] * inv1 + o2[d4 + 2] * inv2),
            tf32f(o1[d4 + 3] * inv1 + o2[d4 + 3] * inv2));
    }
}

__global__ void zero_tail_kernel(float* p, int n) {
    int i = blockIdx.x * blockDim.x + threadIdx.x;
    if (i < n) p[i] = 0.0f;
}

// -------- launch --------
extern "C" void kernel_launch(void* const* d_in, const int* in_sizes, int n_in,
                              void* d_out, int out_size) {
    const float* x      = (const float*)d_in[0];
    const float* Wq_w   = (const float*)d_in[1];
    const float* Wq_A   = (const float*)d_in[2];
    const float* Wq_B   = (const float*)d_in[3];
    const float* Wk_w   = (const float*)d_in[4];
    const float* Wk_A   = (const float*)d_in[5];
    const float* Wk_B   = (const float*)d_in[6];
    const float* Wv_w   = (const float*)d_in[7];
    const float* Wv_A   = (const float*)d_in[8];
    const float* Wv_B   = (const float*)d_in[9];
    const float* proj_w = (const float*)d_in[10];
    const float* hq_w   = (const float*)d_in[11];
    const float* hp_w   = (const float*)d_in[12];
    const float* gate   = (const float*)d_in[13];
    const float* slopes = (const float*)d_in[14];
    float* out = (float*)d_out;

    float *wall, *wcat, *xr, *q, *k, *v, *qh, *cat, *K1, *V1, *K2, *V2;
    cudaGetSymbolAddress((void**)&wall, g_Wall);
    cudaGetSymbolAddress((void**)&wcat, g_Wcat);
    cudaGetSymbolAddress((void**)&xr, g_xr);
    cudaGetSymbolAddress((void**)&q, g_q);
    cudaGetSymbolAddress((void**)&k, g_k);
    cudaGetSymbolAddress((void**)&v, g_v);
    cudaGetSymbolAddress((void**)&qh, g_qh);
    cudaGetSymbolAddress((void**)&cat, g_cat);
    cudaGetSymbolAddress((void**)&K1, g_K1);
    cudaGetSymbolAddress((void**)&V1, g_V1);
    cudaGetSymbolAddress((void**)&K2, g_K2);
    cudaGetSymbolAddress((void**)&V2, g_V2);

    cudaFuncSetAttribute(gemm_tf32_nt_kernel,
                         cudaFuncAttributeMaxDynamicSharedMemorySize, GEMM_SMEM_BYTES);
    cudaFuncSetAttribute(flash_tf32_kernel,
                         cudaFuncAttributeMaxDynamicSharedMemorySize, FLASH_SMEM_BYTES);

    // 1. pre-round inputs; wq/wk/hq rows permuted (pairs-adjacent d)
    fold_lora_kernel<<<(E_ * E_) / 256, 256>>>(Wq_w, Wq_A, Wq_B, wall, 1);
    fold_lora_kernel<<<(E_ * E_) / 256, 256>>>(Wk_w, Wk_A, Wk_B, wall + E_ * E_, 1);
    fold_lora_kernel<<<(E_ * E_) / 256, 256>>>(Wv_w, Wv_A, Wv_B, wall + 2 * E_ * E_, 0);
    round_permrow_kernel<<<(E_ * E_ / 4) / 256, 256>>>(hq_w, wall + 3 * E_ * E_);
    round_tf32_kernel<<<(BTE_ / 4) / 256, 256>>>(x, xr);

    // 2. merged projection GEMM
    gemm_tf32_nt_kernel<<<dim3(32, BT_ / GBM), 256, GEMM_SMEM_BYTES>>>(
        xr, wall, q, k, v, qh, E_, 1);

    // 3. causal attention with alibi -> cat[:, 0:1024]
    flash_tf32_kernel<<<dim3(T_ / 128, B_ * H_), 256, FLASH_SMEM_BYTES>>>(
        q, k, v, slopes, cat);

    // 4. merged hierarchy pooling + small attention -> cat[:, 1024:2048]
    pool_kernel<<<(B_ * 32 * E_ + 255) / 256, 256>>>(k, v, K1, V1, K2, V2);
    hier_attn_kernel<<<dim3(T_ / 32, B_ * H_), 128>>>(qh, K1, V1, K2, V2, gate, cat);

    // 5. pack epilogue weights and ONE merged epilogue GEMM (K = 2048)
    pack_weights_kernel<<<(E_ * E_ / 4) / 256, 256>>>(proj_w, hp_w, wcat);
    gemm_tf32_nt_kernel<<<dim3(8, BT_ / GBM), 256, GEMM_SMEM_BYTES>>>(
        cat, wcat, out, out, out, out, 2 * E_, 0);

    // 6. recon output is exactly zero
    if (out_size > BTE_) {
        int tail = out_size - BTE_;
        zero_tail_kernel<<<(tail + 255) / 256, 256>>>(out + BTE_, tail);
    }
}

// round 17
// speedup vs baseline: 1.0268x; 1.0057x over previous
#include <cuda_runtime.h>
#include <math.h>
#include <stdint.h>

#define B_  4
#define T_  2048
#define E_  1024
#define H_  16
#define DH_ 64
#define BT_ (B_*T_)
#define BTE_ (B_*T_*E_)
#define LOG2E_ 1.4426950408889634f

// -------- scratch (device globals; no allocation allowed) --------
__device__ float g_Wall[4*E_*E_];     // folded+rounded wq* | wk* | wv | hq*  (* = row-permuted)
__device__ float g_Wcat[2*E_*E_];     // packed+rounded [proj|hp], rows of 2048
__device__ float g_xr[BTE_];          // tf32-rounded x
__device__ float g_q[BTE_];           // d-permuted (pairs adjacent)
__device__ float g_k[BTE_];           // d-permuted
__device__ float g_v[BTE_];           // NOT permuted
__device__ float g_qh[BTE_];          // d-permuted
__device__ float g_cat[BT_*2*E_];     // [attn | gate*ctx], rows of 2048
__device__ float g_K1[B_*64*E_];
__device__ float g_V1[B_*64*E_];
__device__ float g_K2[B_*32*E_];
__device__ float g_V2[B_*32*E_];

// -------- helpers --------
__device__ __forceinline__ uint32_t tf32u(float x) {
    uint32_t u;
    asm("cvt.rna.tf32.f32 %0, %1;" : "=r"(u) : "f"(x));
    return u;
}
__device__ __forceinline__ float tf32f(float x) { return __uint_as_float(tf32u(x)); }

// pair-permutation within 8-groups: j -> 2*(j&3) + (j>>2)
__device__ __forceinline__ int cperm(int n) {
    return (n & ~7) | (((n & 3) << 1) | ((n >> 2) & 1));
}

__device__ __forceinline__ void mma_tf32(float* c,
                                         uint32_t a0, uint32_t a1, uint32_t a2, uint32_t a3,
                                         uint32_t b0, uint32_t b1) {
    asm volatile(
        "mma.sync.aligned.m16n8k8.row.col.f32.tf32.tf32.f32 "
        "{%0,%1,%2,%3},{%4,%5,%6,%7},{%8,%9},{%0,%1,%2,%3};"
        : "+f"(c[0]), "+f"(c[1]), "+f"(c[2]), "+f"(c[3])
        : "r"(a0), "r"(a1), "r"(a2), "r"(a3), "r"(b0), "r"(b1));
}

__device__ __forceinline__ void cp_async16(uint32_t smem_addr, const void* gptr) {
    asm volatile("cp.async.cg.shared.global [%0], [%1], 16;\n"
                 :: "r"(smem_addr), "l"(gptr));
}
__device__ __forceinline__ void cp_commit() {
    asm volatile("cp.async.commit_group;\n");
}
__device__ __forceinline__ void cp_wait1() {
    asm volatile("cp.async.wait_group 1;\n");
}

// -------- fold LoRA (tf32-rounded); optional row permutation --------
__global__ void fold_lora_kernel(const float* __restrict__ W,
                                 const float* __restrict__ A,
                                 const float* __restrict__ Bm,
                                 float* __restrict__ Weff, int permute) {
    int idx = blockIdx.x * blockDim.x + threadIdx.x;
    int n = idx >> 10;
    int k = idx & 1023;
    float acc = W[idx];
    #pragma unroll
    for (int r = 0; r < 8; ++r)
        acc += 2.0f * A[n * 8 + r] * Bm[r * E_ + k];
    int nd = permute ? cperm(n) : n;
    Weff[(size_t)nd * E_ + k] = tf32f(acc);
}

// -------- elementwise tf32 rounding --------
__global__ void round_tf32_kernel(const float* __restrict__ src, float* __restrict__ dst) {
    int i = blockIdx.x * blockDim.x + threadIdx.x;
    float4 v = ((const float4*)src)[i];
    ((float4*)dst)[i] = make_float4(tf32f(v.x), tf32f(v.y), tf32f(v.z), tf32f(v.w));
}

// -------- round + row-permute (for hq) --------
__global__ void round_permrow_kernel(const float* __restrict__ src, float* __restrict__ dst) {
    int i = blockIdx.x * blockDim.x + threadIdx.x;
    int n = i >> 8;
    int kq = (i & 255) << 2;
    float4 v = *(const float4*)(src + (size_t)n * E_ + kq);
    *(float4*)(dst + (size_t)cperm(n) * E_ + kq) =
        make_float4(tf32f(v.x), tf32f(v.y), tf32f(v.z), tf32f(v.w));
}

// -------- pack epilogue weights --------
__global__ void pack_weights_kernel(const float* __restrict__ proj,
                                    const float* __restrict__ hp,
                                    float* __restrict__ Wcat) {
    int i = blockIdx.x * blockDim.x + threadIdx.x;
    int n = i >> 8;
    int kq = (i & 255) << 2;
    float4 p = *(const float4*)(proj + (size_t)n * E_ + kq);
    float4 h = *(const float4*)(hp   + (size_t)n * E_ + kq);
    *(float4*)(Wcat + (size_t)n * 2 * E_ + kq) =
        make_float4(tf32f(p.x), tf32f(p.y), tf32f(p.z), tf32f(p.w));
    *(float4*)(Wcat + (size_t)n * 2 * E_ + E_ + kq) =
        make_float4(tf32f(h.x), tf32f(h.y), tf32f(h.z), tf32f(h.w));
}

// ====== tf32 GEMM: 3-stage cp.async pipeline (unchanged hot loop) ======
#define GBM 128
#define GBK 32
#define GST 36
#define GBUF_FLOATS (128*GST)
#define GBUF_BYTES  (GBUF_FLOATS*4)
#define GEMM_SMEM_BYTES (6*GBUF_BYTES)   // 110592

__global__ void __launch_bounds__(256, 2)
gemm_tf32_nt_kernel(const float* __restrict__ A, const float* __restrict__ Bmat,
                    float* __restrict__ C0, float* __restrict__ C1,
                    float* __restrict__ C2, float* __restrict__ C3,
                    int K, int round_out) {
    extern __shared__ float sm[];
    const uint32_t sbase = (uint32_t)__cvta_generic_to_shared(sm);
    const uint32_t bbase = sbase + 3u * GBUF_BYTES;

    const int tid  = threadIdx.x;
    const int warp = tid >> 5;
    const int lane = tid & 31;
    const int wm = warp >> 2;
    const int wn = warp & 3;
    const int g  = lane >> 2;
    const int tg = lane & 3;

    const int bm = blockIdx.y * GBM;
    const int cb = blockIdx.x;
    const int bnW = cb * 128;
    float* Cbuf = (cb < 8) ? C0 : (cb < 16) ? C1 : (cb < 24) ? C2 : C3;
    const int bnC = (cb & 7) * 128;

    float c[4][4][4];
    #pragma unroll
    for (int i = 0; i < 4; ++i)
        #pragma unroll
        for (int j = 0; j < 4; ++j)
            #pragma unroll
            for (int r = 0; r < 4; ++r) c[i][j][r] = 0.0f;

    int lm[4], lkq[4];
    #pragma unroll
    for (int u = 0; u < 4; ++u) {
        int lin = tid + u * 256;
        lm[u]  = lin >> 3;
        lkq[u] = (lin & 7) << 2;
    }

    const int NT = K / GBK;

    #pragma unroll 1
    for (int s = 0; s < 2; ++s) {
        const int kb = s * GBK;
        const uint32_t off = (uint32_t)(s * GBUF_BYTES);
        #pragma unroll
        for (int u = 0; u < 4; ++u) {
            uint32_t da = sbase + off + (uint32_t)(lm[u] * 144 + lkq[u] * 4);
            uint32_t db = bbase + off + (uint32_t)(lm[u] * 144 + lkq[u] * 4);
            cp_async16(da, A    + (size_t)(bm  + lm[u]) * K + kb + lkq[u]);
            cp_async16(db, Bmat + (size_t)(bnW + lm[u]) * K + kb + lkq[u]);
        }
        cp_commit();
    }

    int sc = 0, sw = 2;
    for (int kt = 0; kt < NT; ++kt) {
        cp_wait1();
        __syncthreads();

        if (kt + 2 < NT) {
            const int kb = (kt + 2) * GBK;
            const uint32_t off = (uint32_t)(sw * GBUF_BYTES);
            #pragma unroll
            for (int u = 0; u < 4; ++u) {
                uint32_t da = sbase + off + (uint32_t)(lm[u] * 144 + lkq[u] * 4);
                uint32_t db = bbase + off + (uint32_t)(lm[u] * 144 + lkq[u] * 4);
                cp_async16(da, A    + (size_t)(bm  + lm[u]) * K + kb + lkq[u]);
                cp_async16(db, Bmat + (size_t)(bnW + lm[u]) * K + kb + lkq[u]);
            }
            cp_commit();
            if (++sw == 3) sw = 0;
        }

        const float* Ab = sm + sc * GBUF_FLOATS;
        const float* Bb = sm + 3 * GBUF_FLOATS + sc * GBUF_FLOATS;
        #pragma unroll
        for (int ks = 0; ks < GBK; ks += 8) {
            uint32_t af[4][4], bf[4][2];
            #pragma unroll
            for (int mt = 0; mt < 4; ++mt) {
                int m = wm * 64 + mt * 16;
                af[mt][0] = __float_as_uint(Ab[(m + g    ) * GST + ks + tg    ]);
                af[mt][1] = __float_as_uint(Ab[(m + g + 8) * GST + ks + tg    ]);
                af[mt][2] = __float_as_uint(Ab[(m + g    ) * GST + ks + tg + 4]);
                af[mt][3] = __float_as_uint(Ab[(m + g + 8) * GST + ks + tg + 4]);
            }
            #pragma unroll
            for (int nt = 0; nt < 4; ++nt) {
                int n = wn * 32 + nt * 8;
                bf[nt][0] = __float_as_uint(Bb[(n + g) * GST + ks + tg    ]);
                bf[nt][1] = __float_as_uint(Bb[(n + g) * GST + ks + tg + 4]);
            }
            #pragma unroll
            for (int mt = 0; mt < 4; ++mt)
                #pragma unroll
                for (int nt = 0; nt < 4; ++nt)
                    mma_tf32(c[mt][nt], af[mt][0], af[mt][1], af[mt][2], af[mt][3],
                             bf[nt][0], bf[nt][1]);
        }
        if (++sc == 3) sc = 0;
    }

    #pragma unroll
    for (int mt = 0; mt < 4; ++mt) {
        #pragma unroll
        for (int nt = 0; nt < 4; ++nt) {
            int row0 = bm + wm * 64 + mt * 16 + g;
            int col  = bnC + wn * 32 + nt * 8 + tg * 2;
            float* p0 = Cbuf + (size_t)row0 * E_ + col;
            float* p1 = Cbuf + (size_t)(row0 + 8) * E_ + col;
            float v0 = c[mt][nt][0];
            float v1 = c[mt][nt][1];
            float v2 = c[mt][nt][2];
            float v3 = c[mt][nt][3];
            if (round_out) { v0 = tf32f(v0); v1 = tf32f(v1); v2 = tf32f(v2); v3 = tf32f(v3); }
            p0[0] = v0; p0[1] = v1; p1[0] = v2; p1[1] = v3;
        }
    }
}

// ====== merged attention kernel: flash (blocks x<16) + hier (blocks x>=16) ======
// Flash: key-relabeled V, log2 softmax, 3-stage cp.async.
// Hier: 64 queries/block, 256 threads, runs in flash's scheduling tail.
#define FKSTR 72
#define FVSTR 72
#define FKBUF (64*FKSTR)
#define FVBUF (64*FVSTR)
#define FLASH_SMEM_BYTES (3*(FKBUF+FVBUF)*4)   // 110592
#define NFLASHX 16

__global__ void __launch_bounds__(256, 2)
attn_fused_kernel(const float* __restrict__ Q, const float* __restrict__ K,
                  const float* __restrict__ V, const float* __restrict__ slopes,
                  const float* __restrict__ Qh,
                  const float* __restrict__ K1, const float* __restrict__ V1,
                  const float* __restrict__ K2, const float* __restrict__ V2,
                  const float* __restrict__ gate,
                  float* __restrict__ cat) {
    extern __shared__ float fsm[];

    const int bh = blockIdx.y;
    const int b = bh >> 4;
    const int h = bh & 15;
    const int tid = threadIdx.x;

    if (blockIdx.x < NFLASHX) {
        // ================= FLASH PATH =================
        const uint32_t sbase = (uint32_t)__cvta_generic_to_shared(fsm);
        const uint32_t vbase = sbase + 3u * FKBUF * 4u;
        float* Vsm = fsm + 3 * FKBUF;

        const int bx = NFLASHX - 1 - (int)blockIdx.x;   // heavy blocks first
        const int q0 = bx * 128;
        const int warp = tid >> 5;
        const int lane = tid & 31;
        const int g = lane >> 2;
        const int tg = lane & 3;
        const float SCL2 = 0.125f * LOG2E_;
        const float slope2 = slopes[h] * LOG2E_;

        const int srow = tid >> 2;
        const int scol = (tid & 3) * 16;
        const int vrow = (srow & ~7) | (((srow & 3) << 1) | ((srow >> 2) & 1));

        uint32_t qf[8][4];
        #pragma unroll 1
        for (int half = 0; half < 2; ++half) {
            const float* src = Q + ((size_t)(b * T_ + q0 + half * 64 + srow)) * E_ + h * 64 + scol;
            #pragma unroll
            for (int u = 0; u < 4; ++u)
                *(float4*)&fsm[srow * FKSTR + scol + u * 4] = *(const float4*)(src + u * 4);
            __syncthreads();
            if ((warp >> 2) == half) {
                int lr = (warp & 3) * 16;
                #pragma unroll
                for (int cc = 0; cc < 8; ++cc) {
                    float2 x = *(const float2*)&fsm[(lr + g    ) * FKSTR + cc * 8 + tg * 2];
                    float2 y = *(const float2*)&fsm[(lr + g + 8) * FKSTR + cc * 8 + tg * 2];
                    qf[cc][0] = __float_as_uint(x.x);
                    qf[cc][2] = __float_as_uint(x.y);
                    qf[cc][1] = __float_as_uint(y.x);
                    qf[cc][3] = __float_as_uint(y.y);
                }
            }
            __syncthreads();
        }

        float o[8][4];
        #pragma unroll
        for (int dt = 0; dt < 8; ++dt)
            #pragma unroll
            for (int r = 0; r < 4; ++r) o[dt][r] = 0.0f;

        float m0 = -1e30f, m1 = -1e30f, l0 = 0.0f, l1 = 0.0f;
        const int r0 = q0 + warp * 16 + g;
        const int r1 = r0 + 8;
        const int lastjt_w = 2 * bx + (warp >= 4 ? 1 : 0);
        const int lastjt = 2 * bx + 1;

        #pragma unroll 1
        for (int s = 0; s < 2; ++s) {
            const int nb = s * 64;
            const float* ksrc = K + ((size_t)(b * T_ + nb + srow)) * E_ + h * 64 + scol;
            const float* vsrc = V + ((size_t)(b * T_ + nb + vrow)) * E_ + h * 64 + scol;
            uint32_t kd = sbase + (uint32_t)((s * FKBUF + srow * FKSTR + scol) * 4);
            uint32_t vd = vbase + (uint32_t)((s * FVBUF + srow * FVSTR + scol) * 4);
            #pragma unroll
            for (int u = 0; u < 4; ++u) {
                cp_async16(kd + u * 16, ksrc + u * 4);
                cp_async16(vd + u * 16, vsrc + u * 4);
            }
            cp_commit();
        }

        int sc = 0, sw = 2;
        for (int jt = 0; jt <= lastjt; ++jt) {
            cp_wait1();
            __syncthreads();

            if (jt + 2 <= lastjt) {
                const int n1 = (jt + 2) * 64;
                const float* ksrc = K + ((size_t)(b * T_ + n1 + srow)) * E_ + h * 64 + scol;
                const float* vsrc = V + ((size_t)(b * T_ + n1 + vrow)) * E_ + h * 64 + scol;
                uint32_t kd = sbase + (uint32_t)((sw * FKBUF + srow * FKSTR + scol) * 4);
                uint32_t vd = vbase + (uint32_t)((sw * FVBUF + srow * FVSTR + scol) * 4);
                #pragma unroll
                for (int u = 0; u < 4; ++u) {
                    cp_async16(kd + u * 16, ksrc + u * 4);
                    cp_async16(vd + u * 16, vsrc + u * 4);
                }
                cp_commit();
                if (++sw == 3) sw = 0;
            }

            if (jt <= lastjt_w) {
                const int n0 = jt * 64;
                const float* Kb = fsm + sc * FKBUF;
                const float* Vb = Vsm + sc * FVBUF;

                float sa[8][4];
                #pragma unroll
                for (int nt = 0; nt < 8; ++nt)
                    #pragma unroll
                    for (int r = 0; r < 4; ++r) sa[nt][r] = 0.0f;
                #pragma unroll
                for (int cc = 0; cc < 8; ++cc) {
                    #pragma unroll
                    for (int nt = 0; nt < 8; ++nt) {
                        float2 z = *(const float2*)(Kb + (nt * 8 + g) * FKSTR + cc * 8 + tg * 2);
                        mma_tf32(sa[nt], qf[cc][0], qf[cc][1], qf[cc][2], qf[cc][3],
                                 __float_as_uint(z.x), __float_as_uint(z.y));
                    }
                }

                float mx0 = -1e30f, mx1 = -1e30f;
                const bool diag = (jt == lastjt_w);
                #pragma unroll
                for (int nt = 0; nt < 8; ++nt) {
                    int kc0 = n0 + nt * 8 + tg * 2;
                    float a00 = slope2 * (float)(r0 - kc0);
                    float a01 = a00 - slope2;
                    float a10 = slope2 * (float)(r1 - kc0);
                    float a11 = a10 - slope2;
                    float v00 = fmaf(sa[nt][0], SCL2, a00);
                    float v01 = fmaf(sa[nt][1], SCL2, a01);
                    float v10 = fmaf(sa[nt][2], SCL2, a10);
                    float v11 = fmaf(sa[nt][3], SCL2, a11);
                    if (diag) {
                        if (kc0     > r0) v00 = -1e30f;
                        if (kc0 + 1 > r0) v01 = -1e30f;
                        if (kc0     > r1) v10 = -1e30f;
                        if (kc0 + 1 > r1) v11 = -1e30f;
                    }
                    sa[nt][0] = v00; sa[nt][1] = v01; sa[nt][2] = v10; sa[nt][3] = v11;
                    mx0 = fmaxf(mx0, fmaxf(v00, v01));
                    mx1 = fmaxf(mx1, fmaxf(v10, v11));
                }
                mx0 = fmaxf(mx0, __shfl_xor_sync(0xffffffffu, mx0, 1));
                mx0 = fmaxf(mx0, __shfl_xor_sync(0xffffffffu, mx0, 2));
                mx1 = fmaxf(mx1, __shfl_xor_sync(0xffffffffu, mx1, 1));
                mx1 = fmaxf(mx1, __shfl_xor_sync(0xffffffffu, mx1, 2));

                float mn0 = fmaxf(m0, mx0);
                float mn1 = fmaxf(m1, mx1);
                float sc0 = exp2f(m0 - mn0);
                float sc1 = exp2f(m1 - mn1);
                float rs0 = 0.0f, rs1 = 0.0f;
                #pragma unroll
                for (int nt = 0; nt < 8; ++nt) {
                    float p00 = tf32f(exp2f(sa[nt][0] - mn0));
                    float p01 = tf32f(exp2f(sa[nt][1] - mn0));
                    float p10 = tf32f(exp2f(sa[nt][2] - mn1));
                    float p11 = tf32f(exp2f(sa[nt][3] - mn1));
                    rs0 += p00 + p01;
                    rs1 += p10 + p11;
                    sa[nt][0] = p00; sa[nt][1] = p01; sa[nt][2] = p10; sa[nt][3] = p11;
                }
                rs0 += __shfl_xor_sync(0xffffffffu, rs0, 1);
                rs0 += __shfl_xor_sync(0xffffffffu, rs0, 2);
                rs1 += __shfl_xor_sync(0xffffffffu, rs1, 1);
                rs1 += __shfl_xor_sync(0xffffffffu, rs1, 2);

                l0 = l0 * sc0 + rs0;
                l1 = l1 * sc1 + rs1;
                m0 = mn0; m1 = mn1;
                #pragma unroll
                for (int dt = 0; dt < 8; ++dt) {
                    o[dt][0] *= sc0; o[dt][1] *= sc0;
                    o[dt][2] *= sc1; o[dt][3] *= sc1;
                }

                #pragma unroll
                for (int kc = 0; kc < 8; ++kc) {
                    uint32_t a0 = __float_as_uint(sa[kc][0]);
                    uint32_t a1 = __float_as_uint(sa[kc][2]);
                    uint32_t a2 = __float_as_uint(sa[kc][1]);
                    uint32_t a3 = __float_as_uint(sa[kc][3]);
                    #pragma unroll
                    for (int dt = 0; dt < 8; ++dt) {
                        uint32_t b0 = __float_as_uint(Vb[(kc * 8 + tg    ) * FVSTR + dt * 8 + g]);
                        uint32_t b1 = __float_as_uint(Vb[(kc * 8 + tg + 4) * FVSTR + dt * 8 + g]);
                        mma_tf32(o[dt], a0, a1, a2, a3, b0, b1);
                    }
                }
            }
            if (++sc == 3) sc = 0;
        }

        float il0 = 1.0f / l0, il1 = 1.0f / l1;
        #pragma unroll
        for (int dt = 0; dt < 8; ++dt) {
            float* d0 = cat + ((size_t)(b * T_ + r0)) * (2 * E_) + h * 64 + dt * 8 + tg * 2;
            float* d1 = cat + ((size_t)(b * T_ + r1)) * (2 * E_) + h * 64 + dt * 8 + tg * 2;
            *(float2*)d0 = make_float2(tf32f(o[dt][0] * il0), tf32f(o[dt][1] * il0));
            *(float2*)d1 = make_float2(tf32f(o[dt][2] * il1), tf32f(o[dt][3] * il1));
        }
    } else {
        // ================= HIER PATH (64 queries / block, 256 threads) =================
        float* Qs = fsm;                        // [64][65]
        float* KV = fsm + 64 * 65;              // [96][68]
        float* Ss = fsm + 64 * 65 + 96 * 68;    // [64][97]

        const int tx = (int)blockIdx.x - NFLASHX;
        const int t0 = tx * 64;
        const int q = tid >> 2;
        const int qt = tid & 3;
        const int qc = qt * 16;
        const float SCL2 = 0.125f * LOG2E_;
        const float gsig = 1.0f / (1.0f + __expf(-__ldg(gate)));

        for (int i = tid; i < 64 * 16; i += 256) {
            int r = i >> 4, c4 = (i & 15) << 2;
            float4 v = *(const float4*)(Qh + ((size_t)(b * T_ + t0 + r)) * E_ + h * 64 + c4);
            Qs[r * 65 + c4] = v.x; Qs[r * 65 + c4 + 1] = v.y;
            Qs[r * 65 + c4 + 2] = v.z; Qs[r * 65 + c4 + 3] = v.w;
        }
        for (int i = tid; i < 96 * 16; i += 256) {
            int r = i >> 4, c4 = (i & 15) << 2;
            const float* src = (r < 64)
                ? (K1 + ((size_t)(b * 64 + r)) * E_ + h * 64 + c4)
                : (K2 + ((size_t)(b * 32 + r - 64)) * E_ + h * 64 + c4);
            *(float4*)&KV[r * 68 + c4] = *(const float4*)src;
        }
        __syncthreads();

        for (int m = 0; m < 96; ++m) {
            float s = 0.0f;
            #pragma unroll
            for (int d = 0; d < 16; ++d)
                s = fmaf(Qs[q * 65 + qc + d], KV[m * 68 + qc + d], s);
            s += __shfl_xor_sync(0xffffffffu, s, 1);
            s += __shfl_xor_sync(0xffffffffu, s, 2);
            if (qt == 0) Ss[q * 97 + m] = s * SCL2;
        }
        __syncthreads();

        for (int i = tid; i < 96 * 16; i += 256) {
            int r = i >> 4, c4 = (i & 15) << 2;
            const float* src = (r < 64)
                ? (V1 + ((size_t)(b * 64 + r)) * E_ + h * 64 + c4)
                : (V2 + ((size_t)(b * 32 + r - 64)) * E_ + h * 64 + c4);
            *(float4*)&KV[r * 68 + c4] = *(const float4*)src;
        }
        __syncthreads();

        float mx1 = -1e30f;
        for (int m = 0; m < 64; ++m) mx1 = fmaxf(mx1, Ss[q * 97 + m]);
        float o1[16];
        #pragma unroll
        for (int d = 0; d < 16; ++d) o1[d] = 0.0f;
        float sum1 = 0.0f;
        for (int m = 0; m < 64; ++m) {
            float p = exp2f(Ss[q * 97 + m] - mx1);
            sum1 += p;
            #pragma unroll
            for (int d = 0; d < 16; ++d) o1[d] = fmaf(p, KV[m * 68 + qc + d], o1[d]);
        }
        float mx2 = -1e30f;
        for (int m = 64; m < 96; ++m) mx2 = fmaxf(mx2, Ss[q * 97 + m]);
        float o2[16];
        #pragma unroll
        for (int d = 0; d < 16; ++d) o2[d] = 0.0f;
        float sum2 = 0.0f;
        for (int m = 64; m < 96; ++m) {
            float p = exp2f(Ss[q * 97 + m] - mx2);
            sum2 += p;
            #pragma unroll
            for (int d = 0; d < 16; ++d) o2[d] = fmaf(p, KV[m * 68 + qc + d], o2[d]);
        }
        float inv1 = gsig / sum1, inv2 = gsig / sum2;

        float* dst = cat + ((size_t)(b * T_ + t0 + q)) * (2 * E_) + E_ + h * 64 + qc;
        #pragma unroll
        for (int d4 = 0; d4 < 16; d4 += 4) {
            *(float4*)(dst + d4) = make_float4(
                tf32f(o1[d4 + 0] * inv1 + o2[d4 + 0] * inv2),
                tf32f(o1[d4 + 1] * inv1 + o2[d4 + 1] * inv2),
                tf32f(o1[d4 + 2] * inv1 + o2[d4 + 2] * inv2),
                tf32f(o1[d4 + 3] * inv1 + o2[d4 + 3] * inv2));
        }
    }
}

// -------- merged hierarchy pooling --------
__global__ void pool_kernel(const float* __restrict__ Kf, const float* __restrict__ Vf,
                            float* __restrict__ K1, float* __restrict__ V1,
                            float* __restrict__ K2, float* __restrict__ V2) {
    int idx = blockIdx.x * blockDim.x + threadIdx.x;
    if (idx >= B_ * 32 * E_) return;
    int e = idx & (E_ - 1);
    int p = (idx >> 10) & 31;
    int b = idx >> 15;

    float k1a = 0.0f, v1a = 0.0f, k1b = 0.0f, v1b = 0.0f;
    {
        int t0 = (32 + 2 * p) * 16;
        #pragma unroll
        for (int u = 0; u < 16; ++u) {
            size_t off = ((size_t)(b * T_ + t0 + u) * E_) + e;
            k1a += Kf[off]; v1a += Vf[off];
        }
        t0 += 16;
        #pragma unroll
        for (int u = 0; u < 16; ++u) {
            size_t off = ((size_t)(b * T_ + t0 + u) * E_) + e;
            k1b += Kf[off]; v1b += Vf[off];
        }
    }
    k1a *= (1.0f / 16.0f); v1a *= (1.0f / 16.0f);
    k1b *= (1.0f / 16.0f); v1b *= (1.0f / 16.0f);

    size_t o1 = ((size_t)(b * 64 + 2 * p)) * E_ + e;
    K1[o1] = k1a;        V1[o1] = v1a;
    K1[o1 + E_] = k1b;   V1[o1 + E_] = v1b;

    K2[idx] = 0.5f * (k1a + k1b);
    V2[idx] = 0.5f * (v1a + v1b);
}

__global__ void zero_tail_kernel(float* p, int n) {
    int i = blockIdx.x * blockDim.x + threadIdx.x;
    if (i < n) p[i] = 0.0f;
}

// -------- launch --------
extern "C" void kernel_launch(void* const* d_in, const int* in_sizes, int n_in,
                              void* d_out, int out_size) {
    const float* x      = (const float*)d_in[0];
    const float* Wq_w   = (const float*)d_in[1];
    const float* Wq_A   = (const float*)d_in[2];
    const float* Wq_B   = (const float*)d_in[3];
    const float* Wk_w   = (const float*)d_in[4];
    const float* Wk_A   = (const float*)d_in[5];
    const float* Wk_B   = (const float*)d_in[6];
    const float* Wv_w   = (const float*)d_in[7];
    const float* Wv_A   = (const float*)d_in[8];
    const float* Wv_B   = (const float*)d_in[9];
    const float* proj_w = (const float*)d_in[10];
    const float* hq_w   = (const float*)d_in[11];
    const float* hp_w   = (const float*)d_in[12];
    const float* gate   = (const float*)d_in[13];
    const float* slopes = (const float*)d_in[14];
    float* out = (float*)d_out;

    float *wall, *wcat, *xr, *q, *k, *v, *qh, *cat, *K1, *V1, *K2, *V2;
    cudaGetSymbolAddress((void**)&wall, g_Wall);
    cudaGetSymbolAddress((void**)&wcat, g_Wcat);
    cudaGetSymbolAddress((void**)&xr, g_xr);
    cudaGetSymbolAddress((void**)&q, g_q);
    cudaGetSymbolAddress((void**)&k, g_k);
    cudaGetSymbolAddress((void**)&v, g_v);
    cudaGetSymbolAddress((void**)&qh, g_qh);
    cudaGetSymbolAddress((void**)&cat, g_cat);
    cudaGetSymbolAddress((void**)&K1, g_K1);
    cudaGetSymbolAddress((void**)&V1, g_V1);
    cudaGetSymbolAddress((void**)&K2, g_K2);
    cudaGetSymbolAddress((void**)&V2, g_V2);

    cudaFuncSetAttribute(gemm_tf32_nt_kernel,
                         cudaFuncAttributeMaxDynamicSharedMemorySize, GEMM_SMEM_BYTES);
    cudaFuncSetAttribute(attn_fused_kernel,
                         cudaFuncAttributeMaxDynamicSharedMemorySize, FLASH_SMEM_BYTES);

    // 1. pre-round inputs; wq/wk/hq rows permuted (pairs-adjacent d)
    fold_lora_kernel<<<(E_ * E_) / 256, 256>>>(Wq_w, Wq_A, Wq_B, wall, 1);
    fold_lora_kernel<<<(E_ * E_) / 256, 256>>>(Wk_w, Wk_A, Wk_B, wall + E_ * E_, 1);
    fold_lora_kernel<<<(E_ * E_) / 256, 256>>>(Wv_w, Wv_A, Wv_B, wall + 2 * E_ * E_, 0);
    round_permrow_kernel<<<(E_ * E_ / 4) / 256, 256>>>(hq_w, wall + 3 * E_ * E_);
    round_tf32_kernel<<<(BTE_ / 4) / 256, 256>>>(x, xr);

    // 2. merged projection GEMM
    gemm_tf32_nt_kernel<<<dim3(32, BT_ / GBM), 256, GEMM_SMEM_BYTES>>>(
        xr, wall, q, k, v, qh, E_, 1);

    // 3. pooling (hier inputs) before the fused attention kernel
    pool_kernel<<<(B_ * 32 * E_ + 255) / 256, 256>>>(k, v, K1, V1, K2, V2);

    // 4. FUSED: flash (x<16) + hier (x>=16) in one launch -> both halves of cat
    attn_fused_kernel<<<dim3(NFLASHX + T_ / 64, B_ * H_), 256, FLASH_SMEM_BYTES>>>(
        q, k, v, slopes, qh, K1, V1, K2, V2, gate, cat);

    // 5. pack epilogue weights and ONE merged epilogue GEMM (K = 2048)
    pack_weights_kernel<<<(E_ * E_ / 4) / 256, 256>>>(proj_w, hp_w, wcat);
    gemm_tf32_nt_kernel<<<dim3(8, BT_ / GBM), 256, GEMM_SMEM_BYTES>>>(
        cat, wcat, out, out, out, out, 2 * E_, 0);

    // 6. recon output is exactly zero
    if (out_size > BTE_) {
        int tail = out_size - BTE_;
        zero_tail_kernel<<<(tail + 255) / 256, 256>>>(out + BTE_, tail);
    }
}